// round 4
// baseline (speedup 1.0000x reference)
#include <cuda_runtime.h>
#include <cstdint>

#define SEQ 32
#define HD  2048

// ---------------- scratch (device globals; no allocation) ----------------
__device__ float g_x   [HD  * SEQ];    // residual stream, feature-major [k][s]
__device__ float g_qkv [6144* SEQ];
__device__ float g_t8  [8192* SEQ];
__device__ float g_t2  [HD  * SEQ];
__device__ float g_vc  [HD];
__device__ float g_cc  [HD];
__device__ float g_h1  [1024];
__device__ float g_pstats[64 * SEQ * 2];   // per-block LN partial stats
__device__ float g_gp  [1u << 21];         // split-K partials (8 MB)

// ---------------- GEMM: part[kz][n][s] = sum_k W[n,k]*A[k][s] ------------
// A feature-major [K][32]. W row-major [N][K].
// 64 n-rows/block, 8 warps x 8 rows, lane = token. FFMA2 core, no pack movs.
#define GNPW 8
#define GBN  64
#define GKS  64

__global__ void __launch_bounds__(256) k_gemm(
    const float* __restrict__ W, const float* __restrict__ A,
    float* __restrict__ part, int N, int K, int Kper)
{
    __shared__ float  ws[GBN][GKS];        // 16 KB
    __shared__ float2 xs[GKS / 2][SEQ];    //  8 KB  (k-pair packed)
    const int tid  = threadIdx.x;
    const int lane = tid & 31;
    const int wid  = tid >> 5;
    const int nb   = blockIdx.x * GBN;
    const int kbeg = blockIdx.y * Kper;

    const unsigned xbase = (unsigned)__cvta_generic_to_shared(&xs[0][0]) + lane * 8;
    const unsigned wbase = (unsigned)__cvta_generic_to_shared(&ws[0][0]) + wid * (GNPW * GKS * 4);

    unsigned long long acc[GNPW];
#pragma unroll
    for (int j = 0; j < GNPW; j++) acc[j] = 0ull;

    for (int k0 = kbeg; k0 < kbeg + Kper; k0 += GKS) {
        __syncthreads();
        // stage x chunk as k-pairs: xs[p][l] = (x[k0+2p][l], x[k0+2p+1][l])
#pragma unroll
        for (int i = 0; i < 4; i++) {
            int p = wid + i * 8;
            float a = A[(size_t)(k0 + 2 * p)     * SEQ + lane];
            float b = A[(size_t)(k0 + 2 * p + 1) * SEQ + lane];
            xs[p][lane] = make_float2(a, b);
        }
        // stage weight tile: 64 rows x 64 floats (1024 float4)
#pragma unroll
        for (int i = 0; i < 4; i++) {
            int idx = tid + i * 256;
            int n   = idx >> 4;
            int kv  = idx & 15;
            float4 v = *(const float4*)(W + (size_t)(nb + n) * K + k0 + kv * 4);
            *(float4*)&ws[n][kv * 4] = v;
        }
        __syncthreads();

#pragma unroll
        for (int kk2 = 0; kk2 < GKS / 2; kk2++) {
            unsigned long long xv;
            asm volatile("ld.shared.b64 %0,[%1];" : "=l"(xv)
                         : "r"(xbase + (unsigned)(kk2 * SEQ * 8)));
#pragma unroll
            for (int j = 0; j < GNPW; j++) {
                unsigned long long wv;
                asm volatile("ld.shared.b64 %0,[%1];" : "=l"(wv)
                             : "r"(wbase + (unsigned)(j * GKS * 4 + kk2 * 8)));
                asm("fma.rn.f32x2 %0,%1,%2,%0;" : "+l"(acc[j]) : "l"(wv), "l"(xv));
            }
        }
    }
#pragma unroll
    for (int j = 0; j < GNPW; j++) {
        int n = nb + wid * GNPW + j;
        float lo, hi;
        asm("mov.b64 {%0,%1},%2;" : "=f"(lo), "=f"(hi) : "l"(acc[j]));
        part[((size_t)blockIdx.y * N + n) * SEQ + lane] = lo + hi;
    }
}

// ---- generic split-K reduce (+bias, opt gelu); out_mode 0:[n][32] 1:[s][N]
__global__ void k_gemm_red(const float* __restrict__ part, const float* __restrict__ bias,
                           float* __restrict__ out, int N, int kspl, int act, int out_mode)
{
    int idx = blockIdx.x * 256 + threadIdx.x;
    if (idx >= N * SEQ) return;
    int n = idx >> 5, s = idx & 31;
    float v = bias[n];
    for (int z = 0; z < kspl; z++) v += part[(size_t)z * N * SEQ + idx];
    if (act == 1) v = v * normcdff(v);
    if (out_mode == 0) out[idx] = v;
    else               out[(size_t)s * N + n] = v;
}

// ---- fused reduce + residual add + LN partial stats (N=2048 only) -------
// grid 64 x 256, 4 elems/thread; writes per-block stats to pstats[b][s][2]
__global__ void k_red_ln(const float* __restrict__ part, const float* __restrict__ bias,
                         float* __restrict__ x, float* __restrict__ pstats, int kspl)
{
    __shared__ float ss[8][SEQ], sq[8][SEQ];
    const int t = threadIdx.x, b = blockIdx.x;
    const int lane = t & 31, r = t >> 5;
    float lsum = 0.f, lsq = 0.f;
#pragma unroll
    for (int i = 0; i < 4; i++) {
        int idx = b * 1024 + t + i * 256;
        int n = idx >> 5;
        float v = bias[n];
        for (int z = 0; z < kspl; z++) v += part[(size_t)z * (HD * SEQ) + idx];
        float zv = x[idx] + v;
        x[idx] = zv;
        lsum += zv; lsq += zv * zv;
    }
    ss[r][lane] = lsum; sq[r][lane] = lsq;
    __syncthreads();
    if (t < 32) {
        float a = 0.f, q = 0.f;
#pragma unroll
        for (int rr = 0; rr < 8; rr++) { a += ss[rr][t]; q += sq[rr][t]; }
        pstats[(b * SEQ + t) * 2]     = a;
        pstats[(b * SEQ + t) * 2 + 1] = q;
    }
}

// ---- vector-broadcast residual + LN partial stats (cross-attn) ----------
// grid 16 x 256: z = x + add[k]; pstats[b][s][2]
__global__ void k_ln_part(float* __restrict__ x, const float* __restrict__ add,
                          float* __restrict__ pstats)
{
    __shared__ float rs[8][SEQ], rq[8][SEQ];
    int b = blockIdx.x, t = threadIdx.x;
    int s = t & 31, kr = t >> 5;
    float sum = 0.f, sqv = 0.f;
#pragma unroll
    for (int i = 0; i < 16; i++) {
        int k = b * 128 + i * 8 + kr;
        int idx = k * SEQ + s;
        float z = x[idx] + add[k];
        x[idx] = z;
        sum += z; sqv += z * z;
    }
    rs[kr][s] = sum; rq[kr][s] = sqv;
    __syncthreads();
    if (t < 32) {
        float a = 0.f, q = 0.f;
#pragma unroll
        for (int r = 0; r < 8; r++) { a += rs[r][t]; q += rq[r][t]; }
        pstats[(b * SEQ + t) * 2]     = a;
        pstats[(b * SEQ + t) * 2 + 1] = q;
    }
}

// ---- LN apply: normalize with gamma/beta; sums nparts block-partials ----
__global__ void k_ln_apply(float* __restrict__ x, const float* __restrict__ g,
                           const float* __restrict__ bb, const float* __restrict__ pstats,
                           int nparts)
{
    __shared__ float mean[SEQ], rstd[SEQ];
    int t = threadIdx.x;
    if (t < 32) {
        float a = 0.f, q = 0.f;
        for (int b = 0; b < nparts; b++) {
            a += pstats[(b * SEQ + t) * 2];
            q += pstats[(b * SEQ + t) * 2 + 1];
        }
        float m = a * (1.0f / 2048.0f);
        float v = q * (1.0f / 2048.0f) - m * m;
        mean[t] = m;
        rstd[t] = rsqrtf(v + 1e-5f);
    }
    __syncthreads();
    int base = blockIdx.x * 1024;
#pragma unroll
    for (int i = 0; i < 4; i++) {
        int idx = base + t + i * 256;
        int k = idx >> 5, s = idx & 31;
        x[idx] = (x[idx] - mean[s]) * rstd[s] * g[k] + bb[k];
    }
}

// ---------------- GEMV: vout[n] = act(W[n,:].vin + b[n]) -----------------
__global__ void k_gemv(const float* __restrict__ W, const float* __restrict__ bias,
                       const float* __restrict__ vin, float* __restrict__ vout,
                       int K, int act)
{
    int n    = blockIdx.x * 8 + (threadIdx.x >> 5);
    int lane = threadIdx.x & 31;
    const float* wr = W + (size_t)n * K;
    float s = 0.f;
    for (int k = lane * 4; k < K; k += 128) {
        float4 w = *(const float4*)(wr + k);
        float4 x = *(const float4*)(vin + k);
        s += w.x * x.x + w.y * x.y + w.z * x.z + w.w * x.w;
    }
#pragma unroll
    for (int o = 16; o; o >>= 1) s += __shfl_xor_sync(~0u, s, o);
    if (lane == 0) {
        float v = s + bias[n];
        if (act) v = v * normcdff(v);
        vout[n] = v;
    }
}

// ---------------- size-predictor head: 33-way logits + softmax -----------
__global__ void k_sp2(const float* __restrict__ w2, const float* __restrict__ b2,
                      const float* __restrict__ h1, float* __restrict__ outp)
{
    __shared__ float lg[33];
    int lane = threadIdx.x & 31, wid = threadIdx.x >> 5;
    for (int j = wid; j < 33; j += 8) {
        const float* wr = w2 + (size_t)j * 1024;
        float s = 0.f;
        for (int k = lane * 4; k < 1024; k += 128) {
            float4 w = *(const float4*)(wr + k);
            float4 x = *(const float4*)(h1 + k);
            s += w.x * x.x + w.y * x.y + w.z * x.z + w.w * x.w;
        }
#pragma unroll
        for (int o = 16; o; o >>= 1) s += __shfl_xor_sync(~0u, s, o);
        if (lane == 0) lg[j] = s + b2[j];
    }
    __syncthreads();
    if (threadIdx.x == 0) {
        float m = lg[0];
        for (int j = 1; j < 33; j++) m = fmaxf(m, lg[j]);
        float e[33], se = 0.f;
        for (int j = 0; j < 33; j++) { e[j] = expf(lg[j] - m); se += e[j]; }
        float inv = 1.f / se;
        for (int j = 0; j < 33; j++) outp[j] = e[j] * inv;
    }
}

// ---------------- embedding: x[k][s] = byte_emb[dec[s]][k] + pos_emb[s][k]
__global__ void k_embed(const int* __restrict__ tb, const float* __restrict__ bemb,
                        const float* __restrict__ pemb, float* __restrict__ x)
{
    int idx = blockIdx.x * 256 + threadIdx.x;   // s*H + k
    int s = idx >> 11, k = idx & 2047;
    int d = (s == 0) ? 256 : tb[s - 1];
    x[(size_t)k * SEQ + s] = bemb[(size_t)d * HD + k] + pemb[idx];
}

// ---------------- self-attention, one block per head ---------------------
__global__ void __launch_bounds__(256) k_attn(const float* __restrict__ qkv,
                                              float* __restrict__ o)
{
    __shared__ float qs[128][SEQ], ksm[128][SEQ], sc[SEQ][SEQ + 1];
    const int h = blockIdx.x, t = threadIdx.x;
    const int base_q = (h * 256) * SEQ;
    const int base_k = (2048 + h * 256) * SEQ;
    const int base_v = (4096 + h * 256) * SEQ;
    float p0 = 0, p1 = 0, p2 = 0, p3 = 0;

    for (int dc = 0; dc < 256; dc += 128) {
        __syncthreads();
        const float4* q4 = (const float4*)(qkv + base_q + dc * SEQ);
        const float4* k4 = (const float4*)(qkv + base_k + dc * SEQ);
        float4* qd = (float4*)&qs[0][0];
        float4* kd = (float4*)&ksm[0][0];
#pragma unroll
        for (int i = 0; i < 4; i++) { qd[t + i*256] = q4[t + i*256]; kd[t + i*256] = k4[t + i*256]; }
        __syncthreads();
        int qi0 = t >> 5, ki = t & 31;
        for (int d = 0; d < 128; d++) {
            float kv = ksm[d][ki];
            p0 += qs[d][qi0     ] * kv;
            p1 += qs[d][qi0 +  8] * kv;
            p2 += qs[d][qi0 + 16] * kv;
            p3 += qs[d][qi0 + 24] * kv;
        }
    }
    {
        int qi0 = t >> 5, ki = t & 31;
        sc[qi0     ][ki] = p0 * 0.0625f;
        sc[qi0 +  8][ki] = p1 * 0.0625f;
        sc[qi0 + 16][ki] = p2 * 0.0625f;
        sc[qi0 + 24][ki] = p3 * 0.0625f;
    }
    __syncthreads();
    {
        int wid = t >> 5, lane = t & 31;
        for (int qi = wid; qi < SEQ; qi += 8) {
            float v = sc[qi][lane];
            float m = v;
#pragma unroll
            for (int off = 16; off; off >>= 1) m = fmaxf(m, __shfl_xor_sync(~0u, m, off));
            float e = expf(v - m);
            float ss = e;
#pragma unroll
            for (int off = 16; off; off >>= 1) ss += __shfl_xor_sync(~0u, ss, off);
            sc[qi][lane] = e / ss;
        }
    }
    for (int dc = 0; dc < 256; dc += 128) {
        __syncthreads();
        const float4* v4 = (const float4*)(qkv + base_v + dc * SEQ);
        float4* vd = (float4*)&qs[0][0];
#pragma unroll
        for (int i = 0; i < 4; i++) vd[t + i*256] = v4[t + i*256];
        __syncthreads();
#pragma unroll
        for (int i = 0; i < 16; i++) {
            int idx = t + i * 256;
            int d = idx >> 5, qi = idx & 31;
            float a = 0.f;
#pragma unroll
            for (int ki = 0; ki < SEQ; ki++) a += sc[qi][ki] * qs[d][ki];
            o[(size_t)(h * 256 + dc + d) * SEQ + qi] = a;
        }
    }
}

// ---------------- host-side orchestration --------------------------------
static void run_gemm(const float* W, const float* bias, const float* A, float* out,
                     int N, int K, int kspl, int act, int out_mode, float* gp)
{
    dim3 grid(N / GBN, kspl);
    k_gemm<<<grid, 256>>>(W, A, gp, N, K, K / kspl);
    k_gemm_red<<<(N * SEQ + 255) / 256, 256>>>(gp, bias, out, N, kspl, act, out_mode);
}

static void run_gemm_ln(const float* W, const float* bias, const float* A, float* x,
                        int K, int kspl, float* gp, float* pstats)
{
    dim3 grid(HD / GBN, kspl);   // N = 2048
    k_gemm<<<grid, 256>>>(W, A, gp, HD, K, K / kspl);
    k_red_ln<<<64, 256>>>(gp, bias, x, pstats, kspl);
}

extern "C" void kernel_launch(void* const* d_in, const int* in_sizes, int n_in,
                              void* d_out, int out_size)
{
    const float* pe      = (const float*)d_in[0];
    const int*   tb      = (const int*)  d_in[1];
    const float* sp_w1   = (const float*)d_in[2];
    const float* sp_b1   = (const float*)d_in[3];
    const float* sp_w2   = (const float*)d_in[4];
    const float* sp_b2   = (const float*)d_in[5];
    const float* bemb    = (const float*)d_in[6];
    const float* pemb    = (const float*)d_in[7];
    const float* proj_w  = (const float*)d_in[8];
    const float* proj_b  = (const float*)d_in[9];
    const float* sa_in_w = (const float*)d_in[10];
    const float* sa_in_b = (const float*)d_in[11];
    const float* sa_out_w= (const float*)d_in[12];
    const float* sa_out_b= (const float*)d_in[13];
    const float* ca_in_w = (const float*)d_in[14];
    const float* ca_in_b = (const float*)d_in[15];
    const float* ca_out_w= (const float*)d_in[16];
    const float* ca_out_b= (const float*)d_in[17];
    const float* ff_w1   = (const float*)d_in[18];
    const float* ff_b1   = (const float*)d_in[19];
    const float* ff_w2   = (const float*)d_in[20];
    const float* ff_b2   = (const float*)d_in[21];
    const float* ln1_g   = (const float*)d_in[22];
    const float* ln1_b   = (const float*)d_in[23];
    const float* ln2_g   = (const float*)d_in[24];
    const float* ln2_b   = (const float*)d_in[25];
    const float* ln3_g   = (const float*)d_in[26];
    const float* ln3_b   = (const float*)d_in[27];
    float* out = (float*)d_out;

    float *xp, *qkvp, *t8, *t2, *vc, *cc, *h1, *pstats, *gp;
    cudaGetSymbolAddress((void**)&xp,     g_x);
    cudaGetSymbolAddress((void**)&qkvp,   g_qkv);
    cudaGetSymbolAddress((void**)&t8,     g_t8);
    cudaGetSymbolAddress((void**)&t2,     g_t2);
    cudaGetSymbolAddress((void**)&vc,     g_vc);
    cudaGetSymbolAddress((void**)&cc,     g_cc);
    cudaGetSymbolAddress((void**)&h1,     g_h1);
    cudaGetSymbolAddress((void**)&pstats, g_pstats);
    cudaGetSymbolAddress((void**)&gp,     g_gp);

    // size-predictor head -> out[0:33]
    k_gemv<<<1024 / 8, 256>>>(sp_w1, sp_b1, pe, h1, HD, 1);
    k_sp2 <<<1, 256>>>(sp_w2, sp_b2, h1, out);

    // byte+pos embedding -> g_x (feature-major)
    k_embed<<<(SEQ * HD) / 256, 256>>>(tb, bemb, pemb, xp);

    for (int i = 0; i < 3; i++) {
        const float* saw  = sa_in_w  + (size_t)i * 6144 * HD;
        const float* sab  = sa_in_b  + (size_t)i * 6144;
        const float* sow  = sa_out_w + (size_t)i * HD * HD;
        const float* sob  = sa_out_b + (size_t)i * HD;
        const float* cawv = ca_in_w  + (size_t)i * 6144 * HD + (size_t)4096 * HD; // Wv only
        const float* cabv = ca_in_b  + (size_t)i * 6144 + 4096;
        const float* cow  = ca_out_w + (size_t)i * HD * HD;
        const float* cob  = ca_out_b + (size_t)i * HD;
        const float* f1w  = ff_w1 + (size_t)i * 8192 * HD;
        const float* f1b  = ff_b1 + (size_t)i * 8192;
        const float* f2w  = ff_w2 + (size_t)i * HD * 8192;
        const float* f2b  = ff_b2 + (size_t)i * HD;

        // --- self-attention ---
        run_gemm(saw, sab, xp, qkvp, 6144, HD, 8, 0, 0, gp);        // 768 blocks
        k_attn<<<8, 256>>>(qkvp, t2);
        run_gemm_ln(sow, sob, t2, xp, HD, 16, gp, pstats);          // 512 blocks, fused res+stats
        k_ln_apply<<<64, 256>>>(xp, ln1_g + i * HD, ln1_b + i * HD, pstats, 64);

        // --- cross-attention (softmax over 1 key == identity -> Wv, Wout only) ---
        k_gemv<<<HD / 8, 256>>>(cawv, cabv, pe, vc, HD, 0);
        k_gemv<<<HD / 8, 256>>>(cow,  cob,  vc, cc, HD, 0);
        k_ln_part <<<16, 256>>>(xp, cc, pstats);
        k_ln_apply<<<64, 256>>>(xp, ln2_g + i * HD, ln2_b + i * HD, pstats, 16);

        // --- feed-forward ---
        run_gemm(f1w, f1b, xp, t8, 8192, HD, 4, 1, 0, gp);          // 512 blocks
        run_gemm_ln(f2w, f2b, t8, xp, 8192, 16, gp, pstats);        // 512 blocks
        k_ln_apply<<<64, 256>>>(xp, ln3_g + i * HD, ln3_b + i * HD, pstats, 64);
    }

    // byte logits -> out[33:], row-major [s][256]
    run_gemm(proj_w, proj_b, xp, out + 33, 256, HD, 32, 0, 1, gp);  // 128 blocks
}

// round 6
// speedup vs baseline: 1.5786x; 1.5786x over previous
#include <cuda_runtime.h>
#include <cuda_bf16.h>
#include <cstdint>

#define SEQ 32
#define HD  2048

__device__ __forceinline__ uint32_t smem_to_u32(const void* p) {
    uint32_t a;
    asm("{ .reg .u64 t; cvta.to.shared.u64 t, %1; cvt.u32.u64 %0, t; }" : "=r"(a) : "l"(p));
    return a;
}

#define LDSM4(r, addr) \
    asm volatile("ldmatrix.sync.aligned.m8n8.x4.shared.b16 {%0,%1,%2,%3}, [%4];" \
        : "=r"((r)[0]), "=r"((r)[1]), "=r"((r)[2]), "=r"((r)[3]) : "r"(addr))

#define MMA16816(d, a, b0, b1) \
    asm volatile("mma.sync.aligned.m16n8k16.row.col.f32.bf16.bf16.f32 " \
        "{%0,%1,%2,%3},{%4,%5,%6,%7},{%8,%9},{%0,%1,%2,%3};" \
        : "+f"((d)[0]), "+f"((d)[1]), "+f"((d)[2]), "+f"((d)[3]) \
        : "r"((a)[0]), "r"((a)[1]), "r"((a)[2]), "r"((a)[3]), "r"(b0), "r"(b1))

// hi = top-16-bit truncation packed as bf16x2 (lane0 = first elem)
__device__ __forceinline__ uint32_t pack_hi(float x, float y) {
    return __byte_perm(__float_as_uint(x), __float_as_uint(y), 0x7632);
}
// lo = exact residual vs truncated hi, rn-packed to bf16x2
__device__ __forceinline__ uint32_t pack_lo(float x, float y) {
    float lx = x - __uint_as_float(__float_as_uint(x) & 0xFFFF0000u);
    float ly = y - __uint_as_float(__float_as_uint(y) & 0xFFFF0000u);
    __nv_bfloat162 b = __floats2bfloat162_rn(lx, ly);
    return *reinterpret_cast<uint32_t*>(&b);
}

// ===================== scratch (device globals) ===========================
__device__ float g_x   [SEQ * HD];     // residual, token-major [s][k]
__device__ float g_qkv [SEQ * 6144];
__device__ float g_t8  [SEQ * 8192];
__device__ float g_t2  [SEQ * HD];
__device__ float g_vc  [HD];
__device__ float g_cc  [HD];
__device__ float g_h1  [1024];
__device__ float g_gp  [1u << 23];     // split-K partials (32 MB)

// ===================== HMMA GEMM (bf16 3-split) ===========================
// part[kz][s][n] = sum_{k in slice} W[n][k] * X[s][k]
// 256 thr = 8 warps x 16 weight-rows; W gmem->reg fragments; X via ldmatrix.
#define XPAD 72   // bf16 row stride (144B): conflict-free ldmatrix

__global__ void __launch_bounds__(256) k_hmma(
    const float* __restrict__ W, const float* __restrict__ X,
    float* __restrict__ part, int N, int K, int Kper)
{
    __shared__ __align__(16) __nv_bfloat16 xhi[SEQ][XPAD];
    __shared__ __align__(16) __nv_bfloat16 xlo[SEQ][XPAD];
    const int tid  = threadIdx.x;
    const int lane = tid & 31;
    const int wid  = tid >> 5;
    const int g    = lane >> 2;
    const int tig  = lane & 3;
    const int nb   = blockIdx.x * 128;
    const int kbeg = blockIdx.y * Kper;

    const float* wr0 = W + (size_t)(nb + wid * 16 + g) * K;
    const float* wr1 = wr0 + (size_t)8 * K;

    float acc[4][4];
#pragma unroll
    for (int t = 0; t < 4; t++)
#pragma unroll
        for (int r = 0; r < 4; r++) acc[t][r] = 0.f;

    const uint32_t lrow_hi = smem_to_u32(&xhi[0][0]) + lane * (XPAD * 2);
    const uint32_t lrow_lo = smem_to_u32(&xlo[0][0]) + lane * (XPAD * 2);

    for (int k0 = kbeg; k0 < kbeg + Kper; k0 += 64) {
        __syncthreads();
        // stage X chunk 32x64 fp32 -> bf16 hi/lo (2 float4 per thread)
#pragma unroll
        for (int i = 0; i < 2; i++) {
            int f = tid + i * 256;
            int s = f >> 4, c = f & 15;
            float4 v = *(const float4*)(X + (size_t)s * K + k0 + c * 4);
            uint2 h = make_uint2(pack_hi(v.x, v.y), pack_hi(v.z, v.w));
            uint2 l = make_uint2(pack_lo(v.x, v.y), pack_lo(v.z, v.w));
            *(uint2*)&xhi[s][c * 4] = h;
            *(uint2*)&xlo[s][c * 4] = l;
        }
        __syncthreads();
#pragma unroll
        for (int kk = 0; kk < 64; kk += 16) {
            // W fragment: 4x LDG.64, convert in regs
            float2 w00 = *(const float2*)(wr0 + k0 + kk + 2 * tig);
            float2 w10 = *(const float2*)(wr1 + k0 + kk + 2 * tig);
            float2 w01 = *(const float2*)(wr0 + k0 + kk + 8 + 2 * tig);
            float2 w11 = *(const float2*)(wr1 + k0 + kk + 8 + 2 * tig);
            uint32_t ah[4], al[4];
            ah[0] = pack_hi(w00.x, w00.y); al[0] = pack_lo(w00.x, w00.y);
            ah[1] = pack_hi(w10.x, w10.y); al[1] = pack_lo(w10.x, w10.y);
            ah[2] = pack_hi(w01.x, w01.y); al[2] = pack_lo(w01.x, w01.y);
            ah[3] = pack_hi(w11.x, w11.y); al[3] = pack_lo(w11.x, w11.y);
            // X fragments: 4 n-tiles per ldmatrix.x4 (one k-half each)
            uint32_t bh0[4], bh1[4], bl0[4], bl1[4];
            LDSM4(bh0, lrow_hi + kk * 2);
            LDSM4(bh1, lrow_hi + kk * 2 + 16);
            LDSM4(bl0, lrow_lo + kk * 2);
            LDSM4(bl1, lrow_lo + kk * 2 + 16);
#pragma unroll
            for (int t = 0; t < 4; t++) {
                MMA16816(acc[t], ah, bh0[t], bh1[t]);   // hi*hi
                MMA16816(acc[t], ah, bl0[t], bl1[t]);   // hi*lo
                MMA16816(acc[t], al, bh0[t], bh1[t]);   // lo*hi
            }
        }
    }
    // epilogue: D rows = weight n, cols = token s -> part[(kz*32+s)*N+n]
    float* pb = part + (size_t)blockIdx.y * SEQ * N;
    const int n0 = nb + wid * 16 + g;
#pragma unroll
    for (int t = 0; t < 4; t++) {
        int s0 = t * 8 + 2 * tig;
        pb[(size_t)s0 * N + n0]           = acc[t][0];
        pb[(size_t)(s0 + 1) * N + n0]     = acc[t][1];
        pb[(size_t)s0 * N + n0 + 8]       = acc[t][2];
        pb[(size_t)(s0 + 1) * N + n0 + 8] = acc[t][3];
    }
}

// ---- split-K reduce (+bias, opt exact gelu), token-major -----------------
__global__ void k_red(const float* __restrict__ part, const float* __restrict__ bias,
                      float* __restrict__ out, int N, int kspl, int act)
{
    int idx = blockIdx.x * 256 + threadIdx.x;   // s*N + n
    if (idx >= N * SEQ) return;
    int n = idx % N;
    float v = bias[n];
    for (int z = 0; z < kspl; z++) v += part[(size_t)z * SEQ * N + idx];
    if (act) v = v * normcdff(v);
    out[idx] = v;
}

// ---- fused split-K reduce + residual + LayerNorm (N=2048), 1 block/token
__global__ void __launch_bounds__(256) k_red_ln(
    const float* __restrict__ part, const float* __restrict__ bias,
    float* __restrict__ x, const float* __restrict__ g, const float* __restrict__ b,
    int kspl)
{
    __shared__ float ssum[8], ssq[8], smr[2];
    const int s = blockIdx.x, t = threadIdx.x;
    float z[8];
    float ls = 0.f, lq = 0.f;
#pragma unroll
    for (int j = 0; j < 8; j++) {
        int n = t + j * 256;
        float v = bias[n];
        for (int kz = 0; kz < kspl; kz++)
            v += part[(size_t)kz * SEQ * HD + s * HD + n];
        float zz = x[s * HD + n] + v;
        z[j] = zz; ls += zz; lq += zz * zz;
    }
#pragma unroll
    for (int o = 16; o; o >>= 1) { ls += __shfl_xor_sync(~0u, ls, o); lq += __shfl_xor_sync(~0u, lq, o); }
    if ((t & 31) == 0) { ssum[t >> 5] = ls; ssq[t >> 5] = lq; }
    __syncthreads();
    if (t == 0) {
        float a = 0.f, q = 0.f;
#pragma unroll
        for (int w = 0; w < 8; w++) { a += ssum[w]; q += ssq[w]; }
        float m = a * (1.0f / HD);
        smr[0] = m;
        smr[1] = rsqrtf(q * (1.0f / HD) - m * m + 1e-5f);
    }
    __syncthreads();
    float m = smr[0], r = smr[1];
#pragma unroll
    for (int j = 0; j < 8; j++) {
        int n = t + j * 256;
        x[s * HD + n] = (z[j] - m) * r * g[n] + b[n];
    }
}

// ---- broadcast-vector residual + LayerNorm (cross-attn path) ------------
__global__ void __launch_bounds__(256) k_lnvec(
    float* __restrict__ x, const float* __restrict__ add,
    const float* __restrict__ g, const float* __restrict__ b)
{
    __shared__ float ssum[8], ssq[8], smr[2];
    const int s = blockIdx.x, t = threadIdx.x;
    float z[8];
    float ls = 0.f, lq = 0.f;
#pragma unroll
    for (int j = 0; j < 8; j++) {
        int n = t + j * 256;
        float zz = x[s * HD + n] + add[n];
        z[j] = zz; ls += zz; lq += zz * zz;
    }
#pragma unroll
    for (int o = 16; o; o >>= 1) { ls += __shfl_xor_sync(~0u, ls, o); lq += __shfl_xor_sync(~0u, lq, o); }
    if ((t & 31) == 0) { ssum[t >> 5] = ls; ssq[t >> 5] = lq; }
    __syncthreads();
    if (t == 0) {
        float a = 0.f, q = 0.f;
#pragma unroll
        for (int w = 0; w < 8; w++) { a += ssum[w]; q += ssq[w]; }
        float m = a * (1.0f / HD);
        smr[0] = m;
        smr[1] = rsqrtf(q * (1.0f / HD) - m * m + 1e-5f);
    }
    __syncthreads();
    float m = smr[0], r = smr[1];
#pragma unroll
    for (int j = 0; j < 8; j++) {
        int n = t + j * 256;
        x[s * HD + n] = (z[j] - m) * r * g[n] + b[n];
    }
}

// ---- GEMV (cross-attn collapsed path + size head) ------------------------
__global__ void k_gemv(const float* __restrict__ W, const float* __restrict__ bias,
                       const float* __restrict__ vin, float* __restrict__ vout,
                       int K, int act)
{
    int n    = blockIdx.x * 8 + (threadIdx.x >> 5);
    int lane = threadIdx.x & 31;
    const float* wr = W + (size_t)n * K;
    float s = 0.f;
    for (int k = lane * 4; k < K; k += 128) {
        float4 w = *(const float4*)(wr + k);
        float4 x = *(const float4*)(vin + k);
        s += w.x * x.x + w.y * x.y + w.z * x.z + w.w * x.w;
    }
#pragma unroll
    for (int o = 16; o; o >>= 1) s += __shfl_xor_sync(~0u, s, o);
    if (lane == 0) {
        float v = s + bias[n];
        if (act) v = v * normcdff(v);
        vout[n] = v;
    }
}

// ---- size-predictor: 33 logits + softmax ---------------------------------
__global__ void k_sp2(const float* __restrict__ w2, const float* __restrict__ b2,
                      const float* __restrict__ h1, float* __restrict__ outp)
{
    __shared__ float lg[33];
    int lane = threadIdx.x & 31, wid = threadIdx.x >> 5;
    for (int j = wid; j < 33; j += 8) {
        const float* wr = w2 + (size_t)j * 1024;
        float s = 0.f;
        for (int k = lane * 4; k < 1024; k += 128) {
            float4 w = *(const float4*)(wr + k);
            float4 x = *(const float4*)(h1 + k);
            s += w.x * x.x + w.y * x.y + w.z * x.z + w.w * x.w;
        }
#pragma unroll
        for (int o = 16; o; o >>= 1) s += __shfl_xor_sync(~0u, s, o);
        if (lane == 0) lg[j] = s + b2[j];
    }
    __syncthreads();
    if (threadIdx.x == 0) {
        float m = lg[0];
        for (int j = 1; j < 33; j++) m = fmaxf(m, lg[j]);
        float e[33], se = 0.f;
        for (int j = 0; j < 33; j++) { e[j] = expf(lg[j] - m); se += e[j]; }
        float inv = 1.f / se;
        for (int j = 0; j < 33; j++) outp[j] = e[j] * inv;
    }
}

// ---- embedding (token-major) ---------------------------------------------
__global__ void k_embed(const int* __restrict__ tb, const float* __restrict__ bemb,
                        const float* __restrict__ pemb, float* __restrict__ x)
{
    int idx = blockIdx.x * 256 + threadIdx.x;   // s*H + k
    int s = idx >> 11;
    int k = idx & 2047;
    int d = (s == 0) ? 256 : tb[s - 1];
    x[idx] = bemb[(size_t)d * HD + k] + pemb[idx];
}

// ---- self-attention, token-major, one block per head ---------------------
__global__ void __launch_bounds__(256) k_attn(const float* __restrict__ qkv,
                                              float* __restrict__ o)
{
    __shared__ float qs[32][129], ks[32][129], sc[32][33];
    const int h = blockIdx.x, t = threadIdx.x;
    float p0 = 0, p1 = 0, p2 = 0, p3 = 0;

    for (int dc = 0; dc < 256; dc += 128) {
        __syncthreads();
#pragma unroll
        for (int i = 0; i < 16; i++) {
            int idx = t + i * 256;
            int s = idx >> 7, d = idx & 127;
            qs[s][d] = qkv[s * 6144 + h * 256 + dc + d];
            ks[s][d] = qkv[s * 6144 + 2048 + h * 256 + dc + d];
        }
        __syncthreads();
        int qi = t >> 5, ki = t & 31;
        for (int d = 0; d < 128; d++) {
            float kv = ks[ki][d];
            p0 += qs[qi     ][d] * kv;
            p1 += qs[qi +  8][d] * kv;
            p2 += qs[qi + 16][d] * kv;
            p3 += qs[qi + 24][d] * kv;
        }
    }
    {
        int qi = t >> 5, ki = t & 31;
        sc[qi     ][ki] = p0 * 0.0625f;
        sc[qi +  8][ki] = p1 * 0.0625f;
        sc[qi + 16][ki] = p2 * 0.0625f;
        sc[qi + 24][ki] = p3 * 0.0625f;
    }
    __syncthreads();
    {
        int wid = t >> 5, lane = t & 31;
        for (int qi = wid; qi < 32; qi += 8) {
            float v = sc[qi][lane];
            float m = v;
#pragma unroll
            for (int off = 16; off; off >>= 1) m = fmaxf(m, __shfl_xor_sync(~0u, m, off));
            float e = expf(v - m);
            float ss = e;
#pragma unroll
            for (int off = 16; off; off >>= 1) ss += __shfl_xor_sync(~0u, ss, off);
            sc[qi][lane] = e / ss;
        }
    }
    for (int dc = 0; dc < 256; dc += 128) {
        __syncthreads();
#pragma unroll
        for (int i = 0; i < 16; i++) {
            int idx = t + i * 256;
            int s = idx >> 7, d = idx & 127;
            qs[s][d] = qkv[s * 6144 + 4096 + h * 256 + dc + d];
        }
        __syncthreads();
#pragma unroll
        for (int i = 0; i < 16; i++) {
            int idx = t + i * 256;
            int s = idx >> 7, d = idx & 127;
            float a = 0.f;
#pragma unroll
            for (int ki = 0; ki < 32; ki++) a += sc[s][ki] * qs[ki][d];
            o[s * HD + h * 256 + dc + d] = a;
        }
    }
}

// ===================== host orchestration =================================
static void run_hmma(const float* W, const float* X, float* gp, int N, int K, int kz)
{
    dim3 grid(N / 128, kz);
    k_hmma<<<grid, 256>>>(W, X, gp, N, K, K / kz);
}

extern "C" void kernel_launch(void* const* d_in, const int* in_sizes, int n_in,
                              void* d_out, int out_size)
{
    const float* pe      = (const float*)d_in[0];
    const int*   tb      = (const int*)  d_in[1];
    const float* sp_w1   = (const float*)d_in[2];
    const float* sp_b1   = (const float*)d_in[3];
    const float* sp_w2   = (const float*)d_in[4];
    const float* sp_b2   = (const float*)d_in[5];
    const float* bemb    = (const float*)d_in[6];
    const float* pemb    = (const float*)d_in[7];
    const float* proj_w  = (const float*)d_in[8];
    const float* proj_b  = (const float*)d_in[9];
    const float* sa_in_w = (const float*)d_in[10];
    const float* sa_in_b = (const float*)d_in[11];
    const float* sa_out_w= (const float*)d_in[12];
    const float* sa_out_b= (const float*)d_in[13];
    const float* ca_in_w = (const float*)d_in[14];
    const float* ca_in_b = (const float*)d_in[15];
    const float* ca_out_w= (const float*)d_in[16];
    const float* ca_out_b= (const float*)d_in[17];
    const float* ff_w1   = (const float*)d_in[18];
    const float* ff_b1   = (const float*)d_in[19];
    const float* ff_w2   = (const float*)d_in[20];
    const float* ff_b2   = (const float*)d_in[21];
    const float* ln1_g   = (const float*)d_in[22];
    const float* ln1_b   = (const float*)d_in[23];
    const float* ln2_g   = (const float*)d_in[24];
    const float* ln2_b   = (const float*)d_in[25];
    const float* ln3_g   = (const float*)d_in[26];
    const float* ln3_b   = (const float*)d_in[27];
    float* out = (float*)d_out;

    float *xp, *qkvp, *t8, *t2, *vc, *cc, *h1, *gp;
    cudaGetSymbolAddress((void**)&xp,   g_x);
    cudaGetSymbolAddress((void**)&qkvp, g_qkv);
    cudaGetSymbolAddress((void**)&t8,   g_t8);
    cudaGetSymbolAddress((void**)&t2,   g_t2);
    cudaGetSymbolAddress((void**)&vc,   g_vc);
    cudaGetSymbolAddress((void**)&cc,   g_cc);
    cudaGetSymbolAddress((void**)&h1,   g_h1);
    cudaGetSymbolAddress((void**)&gp,   g_gp);

    // size-predictor head -> out[0:33]
    k_gemv<<<1024 / 8, 256>>>(sp_w1, sp_b1, pe, h1, HD, 1);
    k_sp2 <<<1, 256>>>(sp_w2, sp_b2, h1, out);

    // byte+pos embedding -> x (token-major)
    k_embed<<<(SEQ * HD) / 256, 256>>>(tb, bemb, pemb, xp);

    for (int i = 0; i < 3; i++) {
        const float* saw  = sa_in_w  + (size_t)i * 6144 * HD;
        const float* sab  = sa_in_b  + (size_t)i * 6144;
        const float* sow  = sa_out_w + (size_t)i * HD * HD;
        const float* sob  = sa_out_b + (size_t)i * HD;
        const float* cawv = ca_in_w  + (size_t)i * 6144 * HD + (size_t)4096 * HD; // Wv only
        const float* cabv = ca_in_b  + (size_t)i * 6144 + 4096;
        const float* cow  = ca_out_w + (size_t)i * HD * HD;
        const float* cob  = ca_out_b + (size_t)i * HD;
        const float* f1w  = ff_w1 + (size_t)i * 8192 * HD;
        const float* f1b  = ff_b1 + (size_t)i * 8192;
        const float* f2w  = ff_w2 + (size_t)i * HD * 8192;
        const float* f2b  = ff_b2 + (size_t)i * HD;

        // --- self-attention ---
        run_hmma(saw, xp, gp, 6144, HD, 16);                              // 768 blocks
        k_red<<<(6144 * SEQ) / 256, 256>>>(gp, sab, qkvp, 6144, 16, 0);
        k_attn<<<8, 256>>>(qkvp, t2);
        run_hmma(sow, t2, gp, HD, HD, 32);                                // 512 blocks
        k_red_ln<<<SEQ, 256>>>(gp, sob, xp, ln1_g + i * HD, ln1_b + i * HD, 32);

        // --- cross-attention (1 key -> softmax == 1; only Wv, Wout matter) ---
        k_gemv<<<HD / 8, 256>>>(cawv, cabv, pe, vc, HD, 0);
        k_gemv<<<HD / 8, 256>>>(cow,  cob,  vc, cc, HD, 0);
        k_lnvec<<<SEQ, 256>>>(xp, cc, ln2_g + i * HD, ln2_b + i * HD);

        // --- feed-forward ---
        run_hmma(f1w, xp, gp, 8192, HD, 16);                              // 1024 blocks
        k_red<<<(8192 * SEQ) / 256, 256>>>(gp, f1b, t8, 8192, 16, 1);
        run_hmma(f2w, t8, gp, HD, 8192, 32);                              // 512 blocks
        k_red_ln<<<SEQ, 256>>>(gp, f2b, xp, ln3_g + i * HD, ln3_b + i * HD, 32);
    }

    // byte logits -> out[33:], row-major [s][256]
    run_hmma(proj_w, xp, gp, 256, HD, 32);                                // 64 blocks
    k_red<<<(256 * SEQ) / 256, 256>>>(gp, proj_b, out + 33, 256, 32, 0);
}

// round 7
// speedup vs baseline: 1.6813x; 1.0651x over previous
#include <cuda_runtime.h>
#include <cuda_bf16.h>
#include <cstdint>

#define SEQ 32
#define HD  2048

__device__ __forceinline__ uint32_t smem_to_u32(const void* p) {
    uint32_t a;
    asm("{ .reg .u64 t; cvta.to.shared.u64 t, %1; cvt.u32.u64 %0, t; }" : "=r"(a) : "l"(p));
    return a;
}

#define LDSM4(r, addr) \
    asm volatile("ldmatrix.sync.aligned.m8n8.x4.shared.b16 {%0,%1,%2,%3}, [%4];" \
        : "=r"((r)[0]), "=r"((r)[1]), "=r"((r)[2]), "=r"((r)[3]) : "r"(addr))

#define MMA16816(d, a, b0, b1) \
    asm volatile("mma.sync.aligned.m16n8k16.row.col.f32.bf16.bf16.f32 " \
        "{%0,%1,%2,%3},{%4,%5,%6,%7},{%8,%9},{%0,%1,%2,%3};" \
        : "+f"((d)[0]), "+f"((d)[1]), "+f"((d)[2]), "+f"((d)[3]) \
        : "r"((a)[0]), "r"((a)[1]), "r"((a)[2]), "r"((a)[3]), "r"(b0), "r"(b1))

// hi = top-16-bit truncation packed as bf16x2 (lane0 = first elem)
__device__ __forceinline__ uint32_t pack_hi(float x, float y) {
    return __byte_perm(__float_as_uint(x), __float_as_uint(y), 0x7632);
}
// lo = exact residual vs truncated hi, rn-packed to bf16x2
__device__ __forceinline__ uint32_t pack_lo(float x, float y) {
    float lx = x - __uint_as_float(__float_as_uint(x) & 0xFFFF0000u);
    float ly = y - __uint_as_float(__float_as_uint(y) & 0xFFFF0000u);
    __nv_bfloat162 b = __floats2bfloat162_rn(lx, ly);
    return *reinterpret_cast<uint32_t*>(&b);
}

// ===================== scratch (device globals) ===========================
__device__ float g_x   [SEQ * HD];     // residual, token-major [s][k]
__device__ float g_qkv [SEQ * 6144];
__device__ float g_t8  [SEQ * 8192];
__device__ float g_t2  [SEQ * HD];
__device__ float g_vc  [HD];
__device__ float g_cc  [HD];
__device__ float g_h1  [1024];
__device__ float g_gp  [1u << 23];     // split-K partials (32 MB)

// ===================== HMMA GEMM (bf16 3-split) ===========================
// part[kz][s][n] = sum_{k in slice} W[n][k] * X[s][k]
// 128 thr = 4 warps x 16 weight-rows (NTILE=64). Whole X k-slice staged once;
// mainloop is sync-free: LDG W -> pack -> ldmatrix -> 12 HMMA per k16.
#define XPAD 264   // bf16 row stride 528B: ldmatrix conflict-free, Kper<=256

__global__ void __launch_bounds__(128) k_hmma(
    const float* __restrict__ W, const float* __restrict__ X,
    float* __restrict__ part, int N, int K, int Kper)
{
    __shared__ __align__(16) __nv_bfloat16 xhi[SEQ][XPAD];
    __shared__ __align__(16) __nv_bfloat16 xlo[SEQ][XPAD];
    const int tid  = threadIdx.x;
    const int lane = tid & 31;
    const int wid  = tid >> 5;
    const int g    = lane >> 2;
    const int tig  = lane & 3;
    const int nb   = blockIdx.x * 64;
    const int kbeg = blockIdx.y * Kper;

    // ---- stage entire X k-slice (32 x Kper fp32 -> bf16 hi/lo) ----
    const int nf4 = Kper >> 2;   // float4 per token row
    for (int f = tid; f < SEQ * nf4; f += 128) {
        int s = f / nf4, c = f - s * nf4;
        float4 v = *(const float4*)(X + (size_t)s * K + kbeg + c * 4);
        uint2 h = make_uint2(pack_hi(v.x, v.y), pack_hi(v.z, v.w));
        uint2 l = make_uint2(pack_lo(v.x, v.y), pack_lo(v.z, v.w));
        *(uint2*)&xhi[s][c * 4] = h;
        *(uint2*)&xlo[s][c * 4] = l;
    }
    __syncthreads();

    const float* wr0 = W + (size_t)(nb + wid * 16 + g) * K + kbeg;
    const float* wr1 = wr0 + (size_t)8 * K;

    float acc[4][4];
#pragma unroll
    for (int t = 0; t < 4; t++)
#pragma unroll
        for (int r = 0; r < 4; r++) acc[t][r] = 0.f;

    const uint32_t lrow_hi = smem_to_u32(&xhi[0][0]) + lane * (XPAD * 2);
    const uint32_t lrow_lo = smem_to_u32(&xlo[0][0]) + lane * (XPAD * 2);

#pragma unroll 4
    for (int kk = 0; kk < Kper; kk += 16) {
        // W fragment: 4x LDG.64, convert in regs (no smem for W)
        float2 w00 = *(const float2*)(wr0 + kk + 2 * tig);
        float2 w10 = *(const float2*)(wr1 + kk + 2 * tig);
        float2 w01 = *(const float2*)(wr0 + kk + 8 + 2 * tig);
        float2 w11 = *(const float2*)(wr1 + kk + 8 + 2 * tig);
        uint32_t ah[4], al[4];
        ah[0] = pack_hi(w00.x, w00.y); al[0] = pack_lo(w00.x, w00.y);
        ah[1] = pack_hi(w10.x, w10.y); al[1] = pack_lo(w10.x, w10.y);
        ah[2] = pack_hi(w01.x, w01.y); al[2] = pack_lo(w01.x, w01.y);
        ah[3] = pack_hi(w11.x, w11.y); al[3] = pack_lo(w11.x, w11.y);
        uint32_t bh0[4], bh1[4], bl0[4], bl1[4];
        LDSM4(bh0, lrow_hi + kk * 2);
        LDSM4(bh1, lrow_hi + kk * 2 + 16);
        LDSM4(bl0, lrow_lo + kk * 2);
        LDSM4(bl1, lrow_lo + kk * 2 + 16);
#pragma unroll
        for (int t = 0; t < 4; t++) {
            MMA16816(acc[t], ah, bh0[t], bh1[t]);   // hi*hi
            MMA16816(acc[t], ah, bl0[t], bl1[t]);   // hi*lo
            MMA16816(acc[t], al, bh0[t], bh1[t]);   // lo*hi
        }
    }
    // epilogue: D rows = weight n, cols = token s -> part[(kz*32+s)*N+n]
    float* pb = part + (size_t)blockIdx.y * SEQ * N;
    const int n0 = nb + wid * 16 + g;
#pragma unroll
    for (int t = 0; t < 4; t++) {
        int s0 = t * 8 + 2 * tig;
        pb[(size_t)s0 * N + n0]           = acc[t][0];
        pb[(size_t)(s0 + 1) * N + n0]     = acc[t][1];
        pb[(size_t)s0 * N + n0 + 8]       = acc[t][2];
        pb[(size_t)(s0 + 1) * N + n0 + 8] = acc[t][3];
    }
}

// ---- split-K reduce, float4 (+bias, opt exact gelu), token-major ---------
__global__ void k_red4(const float4* __restrict__ part, const float4* __restrict__ bias,
                       float4* __restrict__ out, int N4, int kspl, int act)
{
    int idx = blockIdx.x * 256 + threadIdx.x;   // float4 index over s*N4
    if (idx >= N4 * SEQ) return;
    int n = idx % N4;
    float4 v = bias[n];
    for (int z = 0; z < kspl; z++) {
        float4 p = part[(size_t)z * SEQ * N4 + idx];
        v.x += p.x; v.y += p.y; v.z += p.z; v.w += p.w;
    }
    if (act) {
        v.x *= normcdff(v.x); v.y *= normcdff(v.y);
        v.z *= normcdff(v.z); v.w *= normcdff(v.w);
    }
    out[idx] = v;
}

// ---- scalar split-K reduce (unaligned output: proj head) -----------------
__global__ void k_red_s(const float* __restrict__ part, const float* __restrict__ bias,
                        float* __restrict__ out, int N, int kspl)
{
    int idx = blockIdx.x * 256 + threadIdx.x;
    if (idx >= N * SEQ) return;
    int n = idx % N;
    float v = bias[n];
    for (int z = 0; z < kspl; z++) v += part[(size_t)z * SEQ * N + idx];
    out[idx] = v;
}

// ---- fused split-K reduce + residual + LayerNorm (N=2048), 1 block/token
__global__ void __launch_bounds__(256) k_red_ln(
    const float4* __restrict__ part, const float4* __restrict__ bias,
    float4* __restrict__ x, const float4* __restrict__ g, const float4* __restrict__ b,
    int kspl)
{
    __shared__ float ssum[8], ssq[8], smr[2];
    const int s = blockIdx.x, t = threadIdx.x;
    float4 z[2];
    float ls = 0.f, lq = 0.f;
#pragma unroll
    for (int j = 0; j < 2; j++) {
        int n4 = t + j * 256;                 // 0..511
        size_t base = (size_t)s * 512 + n4;
        float4 v = bias[n4];
        for (int kz = 0; kz < kspl; kz++) {
            float4 p = part[(size_t)kz * SEQ * 512 + base];
            v.x += p.x; v.y += p.y; v.z += p.z; v.w += p.w;
        }
        float4 xx = x[base];
        float4 zz = make_float4(xx.x + v.x, xx.y + v.y, xx.z + v.z, xx.w + v.w);
        z[j] = zz;
        ls += zz.x + zz.y + zz.z + zz.w;
        lq += zz.x * zz.x + zz.y * zz.y + zz.z * zz.z + zz.w * zz.w;
    }
#pragma unroll
    for (int o = 16; o; o >>= 1) { ls += __shfl_xor_sync(~0u, ls, o); lq += __shfl_xor_sync(~0u, lq, o); }
    if ((t & 31) == 0) { ssum[t >> 5] = ls; ssq[t >> 5] = lq; }
    __syncthreads();
    if (t == 0) {
        float a = 0.f, q = 0.f;
#pragma unroll
        for (int w = 0; w < 8; w++) { a += ssum[w]; q += ssq[w]; }
        float m = a * (1.0f / HD);
        smr[0] = m;
        smr[1] = rsqrtf(q * (1.0f / HD) - m * m + 1e-5f);
    }
    __syncthreads();
    float m = smr[0], r = smr[1];
#pragma unroll
    for (int j = 0; j < 2; j++) {
        int n4 = t + j * 256;
        size_t base = (size_t)s * 512 + n4;
        float4 gg = g[n4], bb = b[n4], zz = z[j];
        x[base] = make_float4((zz.x - m) * r * gg.x + bb.x, (zz.y - m) * r * gg.y + bb.y,
                              (zz.z - m) * r * gg.z + bb.z, (zz.w - m) * r * gg.w + bb.w);
    }
}

// ---- broadcast-vector residual + LayerNorm (cross-attn path) -------------
__global__ void __launch_bounds__(256) k_lnvec(
    float4* __restrict__ x, const float4* __restrict__ add,
    const float4* __restrict__ g, const float4* __restrict__ b)
{
    __shared__ float ssum[8], ssq[8], smr[2];
    const int s = blockIdx.x, t = threadIdx.x;
    float4 z[2];
    float ls = 0.f, lq = 0.f;
#pragma unroll
    for (int j = 0; j < 2; j++) {
        int n4 = t + j * 256;
        size_t base = (size_t)s * 512 + n4;
        float4 xx = x[base], a = add[n4];
        float4 zz = make_float4(xx.x + a.x, xx.y + a.y, xx.z + a.z, xx.w + a.w);
        z[j] = zz;
        ls += zz.x + zz.y + zz.z + zz.w;
        lq += zz.x * zz.x + zz.y * zz.y + zz.z * zz.z + zz.w * zz.w;
    }
#pragma unroll
    for (int o = 16; o; o >>= 1) { ls += __shfl_xor_sync(~0u, ls, o); lq += __shfl_xor_sync(~0u, lq, o); }
    if ((t & 31) == 0) { ssum[t >> 5] = ls; ssq[t >> 5] = lq; }
    __syncthreads();
    if (t == 0) {
        float a = 0.f, q = 0.f;
#pragma unroll
        for (int w = 0; w < 8; w++) { a += ssum[w]; q += ssq[w]; }
        float m = a * (1.0f / HD);
        smr[0] = m;
        smr[1] = rsqrtf(q * (1.0f / HD) - m * m + 1e-5f);
    }
    __syncthreads();
    float m = smr[0], r = smr[1];
#pragma unroll
    for (int j = 0; j < 2; j++) {
        int n4 = t + j * 256;
        size_t base = (size_t)s * 512 + n4;
        float4 gg = g[n4], bb = b[n4], zz = z[j];
        x[base] = make_float4((zz.x - m) * r * gg.x + bb.x, (zz.y - m) * r * gg.y + bb.y,
                              (zz.z - m) * r * gg.z + bb.z, (zz.w - m) * r * gg.w + bb.w);
    }
}

// ---- GEMV (cross-attn collapsed path + size head) ------------------------
__global__ void k_gemv(const float* __restrict__ W, const float* __restrict__ bias,
                       const float* __restrict__ vin, float* __restrict__ vout,
                       int K, int act)
{
    int n    = blockIdx.x * 8 + (threadIdx.x >> 5);
    int lane = threadIdx.x & 31;
    const float* wr = W + (size_t)n * K;
    float s = 0.f;
    for (int k = lane * 4; k < K; k += 128) {
        float4 w = *(const float4*)(wr + k);
        float4 x = *(const float4*)(vin + k);
        s += w.x * x.x + w.y * x.y + w.z * x.z + w.w * x.w;
    }
#pragma unroll
    for (int o = 16; o; o >>= 1) s += __shfl_xor_sync(~0u, s, o);
    if (lane == 0) {
        float v = s + bias[n];
        if (act) v = v * normcdff(v);
        vout[n] = v;
    }
}

// ---- size-predictor: 33 logits + softmax ---------------------------------
__global__ void k_sp2(const float* __restrict__ w2, const float* __restrict__ b2,
                      const float* __restrict__ h1, float* __restrict__ outp)
{
    __shared__ float lg[33];
    int lane = threadIdx.x & 31, wid = threadIdx.x >> 5;
    for (int j = wid; j < 33; j += 8) {
        const float* wr = w2 + (size_t)j * 1024;
        float s = 0.f;
        for (int k = lane * 4; k < 1024; k += 128) {
            float4 w = *(const float4*)(wr + k);
            float4 x = *(const float4*)(h1 + k);
            s += w.x * x.x + w.y * x.y + w.z * x.z + w.w * x.w;
        }
#pragma unroll
        for (int o = 16; o; o >>= 1) s += __shfl_xor_sync(~0u, s, o);
        if (lane == 0) lg[j] = s + b2[j];
    }
    __syncthreads();
    if (threadIdx.x == 0) {
        float m = lg[0];
        for (int j = 1; j < 33; j++) m = fmaxf(m, lg[j]);
        float e[33], se = 0.f;
        for (int j = 0; j < 33; j++) { e[j] = expf(lg[j] - m); se += e[j]; }
        float inv = 1.f / se;
        for (int j = 0; j < 33; j++) outp[j] = e[j] * inv;
    }
}

// ---- embedding (token-major) ---------------------------------------------
__global__ void k_embed(const int* __restrict__ tb, const float* __restrict__ bemb,
                        const float* __restrict__ pemb, float* __restrict__ x)
{
    int idx = blockIdx.x * 256 + threadIdx.x;   // s*H + k
    int s = idx >> 11;
    int k = idx & 2047;
    int d = (s == 0) ? 256 : tb[s - 1];
    x[idx] = bemb[(size_t)d * HD + k] + pemb[idx];
}

// ---- self-attention, token-major, one block per head ---------------------
__global__ void __launch_bounds__(256) k_attn(const float* __restrict__ qkv,
                                              float* __restrict__ o)
{
    __shared__ float qs[32][129], ks[32][129], sc[32][33];
    const int h = blockIdx.x, t = threadIdx.x;
    float p0 = 0, p1 = 0, p2 = 0, p3 = 0;

    for (int dc = 0; dc < 256; dc += 128) {
        __syncthreads();
#pragma unroll
        for (int i = 0; i < 16; i++) {
            int idx = t + i * 256;
            int s = idx >> 7, d = idx & 127;
            qs[s][d] = qkv[s * 6144 + h * 256 + dc + d];
            ks[s][d] = qkv[s * 6144 + 2048 + h * 256 + dc + d];
        }
        __syncthreads();
        int qi = t >> 5, ki = t & 31;
        for (int d = 0; d < 128; d++) {
            float kv = ks[ki][d];
            p0 += qs[qi     ][d] * kv;
            p1 += qs[qi +  8][d] * kv;
            p2 += qs[qi + 16][d] * kv;
            p3 += qs[qi + 24][d] * kv;
        }
    }
    {
        int qi = t >> 5, ki = t & 31;
        sc[qi     ][ki] = p0 * 0.0625f;
        sc[qi +  8][ki] = p1 * 0.0625f;
        sc[qi + 16][ki] = p2 * 0.0625f;
        sc[qi + 24][ki] = p3 * 0.0625f;
    }
    __syncthreads();
    {
        int wid = t >> 5, lane = t & 31;
        for (int qi = wid; qi < 32; qi += 8) {
            float v = sc[qi][lane];
            float m = v;
#pragma unroll
            for (int off = 16; off; off >>= 1) m = fmaxf(m, __shfl_xor_sync(~0u, m, off));
            float e = expf(v - m);
            float ss = e;
#pragma unroll
            for (int off = 16; off; off >>= 1) ss += __shfl_xor_sync(~0u, ss, off);
            sc[qi][lane] = e / ss;
        }
    }
    for (int dc = 0; dc < 256; dc += 128) {
        __syncthreads();
#pragma unroll
        for (int i = 0; i < 16; i++) {
            int idx = t + i * 256;
            int s = idx >> 7, d = idx & 127;
            qs[s][d] = qkv[s * 6144 + 4096 + h * 256 + dc + d];
        }
        __syncthreads();
#pragma unroll
        for (int i = 0; i < 16; i++) {
            int idx = t + i * 256;
            int s = idx >> 7, d = idx & 127;
            float a = 0.f;
#pragma unroll
            for (int ki = 0; ki < 32; ki++) a += sc[s][ki] * qs[ki][d];
            o[s * HD + h * 256 + dc + d] = a;
        }
    }
}

// ===================== host orchestration =================================
static void run_hmma(const float* W, const float* X, float* gp, int N, int K, int kz)
{
    dim3 grid(N / 64, kz);
    k_hmma<<<grid, 128>>>(W, X, gp, N, K, K / kz);
}

extern "C" void kernel_launch(void* const* d_in, const int* in_sizes, int n_in,
                              void* d_out, int out_size)
{
    const float* pe      = (const float*)d_in[0];
    const int*   tb      = (const int*)  d_in[1];
    const float* sp_w1   = (const float*)d_in[2];
    const float* sp_b1   = (const float*)d_in[3];
    const float* sp_w2   = (const float*)d_in[4];
    const float* sp_b2   = (const float*)d_in[5];
    const float* bemb    = (const float*)d_in[6];
    const float* pemb    = (const float*)d_in[7];
    const float* proj_w  = (const float*)d_in[8];
    const float* proj_b  = (const float*)d_in[9];
    const float* sa_in_w = (const float*)d_in[10];
    const float* sa_in_b = (const float*)d_in[11];
    const float* sa_out_w= (const float*)d_in[12];
    const float* sa_out_b= (const float*)d_in[13];
    const float* ca_in_w = (const float*)d_in[14];
    const float* ca_in_b = (const float*)d_in[15];
    const float* ca_out_w= (const float*)d_in[16];
    const float* ca_out_b= (const float*)d_in[17];
    const float* ff_w1   = (const float*)d_in[18];
    const float* ff_b1   = (const float*)d_in[19];
    const float* ff_w2   = (const float*)d_in[20];
    const float* ff_b2   = (const float*)d_in[21];
    const float* ln1_g   = (const float*)d_in[22];
    const float* ln1_b   = (const float*)d_in[23];
    const float* ln2_g   = (const float*)d_in[24];
    const float* ln2_b   = (const float*)d_in[25];
    const float* ln3_g   = (const float*)d_in[26];
    const float* ln3_b   = (const float*)d_in[27];
    float* out = (float*)d_out;

    float *xp, *qkvp, *t8, *t2, *vc, *cc, *h1, *gp;
    cudaGetSymbolAddress((void**)&xp,   g_x);
    cudaGetSymbolAddress((void**)&qkvp, g_qkv);
    cudaGetSymbolAddress((void**)&t8,   g_t8);
    cudaGetSymbolAddress((void**)&t2,   g_t2);
    cudaGetSymbolAddress((void**)&vc,   g_vc);
    cudaGetSymbolAddress((void**)&cc,   g_cc);
    cudaGetSymbolAddress((void**)&h1,   g_h1);
    cudaGetSymbolAddress((void**)&gp,   g_gp);

    // size-predictor head -> out[0:33]
    k_gemv<<<1024 / 8, 256>>>(sp_w1, sp_b1, pe, h1, HD, 1);
    k_sp2 <<<1, 256>>>(sp_w2, sp_b2, h1, out);

    // byte+pos embedding -> x (token-major)
    k_embed<<<(SEQ * HD) / 256, 256>>>(tb, bemb, pemb, xp);

    for (int i = 0; i < 3; i++) {
        const float* saw  = sa_in_w  + (size_t)i * 6144 * HD;
        const float* sab  = sa_in_b  + (size_t)i * 6144;
        const float* sow  = sa_out_w + (size_t)i * HD * HD;
        const float* sob  = sa_out_b + (size_t)i * HD;
        const float* cawv = ca_in_w  + (size_t)i * 6144 * HD + (size_t)4096 * HD; // Wv only
        const float* cabv = ca_in_b  + (size_t)i * 6144 + 4096;
        const float* cow  = ca_out_w + (size_t)i * HD * HD;
        const float* cob  = ca_out_b + (size_t)i * HD;
        const float* f1w  = ff_w1 + (size_t)i * 8192 * HD;
        const float* f1b  = ff_b1 + (size_t)i * 8192;
        const float* f2w  = ff_w2 + (size_t)i * HD * 8192;
        const float* f2b  = ff_b2 + (size_t)i * HD;

        // --- self-attention ---
        run_hmma(saw, xp, gp, 6144, HD, 8);                               // 768 blocks, Kper=256
        k_red4<<<(6144 * SEQ / 4 + 255) / 256, 256>>>((const float4*)gp, (const float4*)sab,
                                                      (float4*)qkvp, 6144 / 4, 8, 0);
        k_attn<<<8, 256>>>(qkvp, t2);
        run_hmma(sow, t2, gp, HD, HD, 16);                                // 512 blocks, Kper=128
        k_red_ln<<<SEQ, 256>>>((const float4*)gp, (const float4*)sob, (float4*)xp,
                               (const float4*)(ln1_g + i * HD), (const float4*)(ln1_b + i * HD), 16);

        // --- cross-attention (1 key -> softmax == 1; only Wv, Wout matter) ---
        k_gemv<<<HD / 8, 256>>>(cawv, cabv, pe, vc, HD, 0);
        k_gemv<<<HD / 8, 256>>>(cow,  cob,  vc, cc, HD, 0);
        k_lnvec<<<SEQ, 256>>>((float4*)xp, (const float4*)cc,
                              (const float4*)(ln2_g + i * HD), (const float4*)(ln2_b + i * HD));

        // --- feed-forward ---
        run_hmma(f1w, xp, gp, 8192, HD, 8);                               // 1024 blocks, Kper=256
        k_red4<<<(8192 * SEQ / 4 + 255) / 256, 256>>>((const float4*)gp, (const float4*)f1b,
                                                      (float4*)t8, 8192 / 4, 8, 1);
        run_hmma(f2w, t8, gp, HD, 8192, 32);                              // 1024 blocks, Kper=256
        k_red_ln<<<SEQ, 256>>>((const float4*)gp, (const float4*)f2b, (float4*)xp,
                               (const float4*)(ln3_g + i * HD), (const float4*)(ln3_b + i * HD), 32);
    }

    // byte logits -> out[33:], row-major [s][256]
    run_hmma(proj_w, xp, gp, 256, HD, 32);                                // 128 blocks, Kper=64
    k_red_s<<<(256 * SEQ + 255) / 256, 256>>>(gp, proj_b, out + 33, 256, 32);
}

// round 8
// speedup vs baseline: 1.7189x; 1.0224x over previous
#include <cuda_runtime.h>
#include <cuda_bf16.h>
#include <cstdint>

#define SEQ 32
#define HD  2048

__device__ __forceinline__ uint32_t smem_to_u32(const void* p) {
    uint32_t a;
    asm("{ .reg .u64 t; cvta.to.shared.u64 t, %1; cvt.u32.u64 %0, t; }" : "=r"(a) : "l"(p));
    return a;
}

#define LDSM4(r, addr) \
    asm volatile("ldmatrix.sync.aligned.m8n8.x4.shared.b16 {%0,%1,%2,%3}, [%4];" \
        : "=r"((r)[0]), "=r"((r)[1]), "=r"((r)[2]), "=r"((r)[3]) : "r"(addr))

#define MMA16816(d, a, b0, b1) \
    asm volatile("mma.sync.aligned.m16n8k16.row.col.f32.bf16.bf16.f32 " \
        "{%0,%1,%2,%3},{%4,%5,%6,%7},{%8,%9},{%0,%1,%2,%3};" \
        : "+f"((d)[0]), "+f"((d)[1]), "+f"((d)[2]), "+f"((d)[3]) \
        : "r"((a)[0]), "r"((a)[1]), "r"((a)[2]), "r"((a)[3]), "r"(b0), "r"(b1))

// hi = top-16-bit truncation packed as bf16x2 (lane0 = first elem)
__device__ __forceinline__ uint32_t pack_hi(float x, float y) {
    return __byte_perm(__float_as_uint(x), __float_as_uint(y), 0x7632);
}
// lo = exact residual vs truncated hi, rn-packed to bf16x2
__device__ __forceinline__ uint32_t pack_lo(float x, float y) {
    float lx = x - __uint_as_float(__float_as_uint(x) & 0xFFFF0000u);
    float ly = y - __uint_as_float(__float_as_uint(y) & 0xFFFF0000u);
    __nv_bfloat162 b = __floats2bfloat162_rn(lx, ly);
    return *reinterpret_cast<uint32_t*>(&b);
}

// ===================== scratch (device globals) ===========================
__device__ float g_x   [SEQ * HD];     // residual, token-major [s][k]
__device__ float g_qkv [SEQ * 6144];
__device__ float g_t8  [SEQ * 8192];
__device__ float g_t2  [SEQ * HD];
__device__ float g_vc  [HD];
__device__ float g_cc  [HD];
__device__ float g_h1  [1024];
__device__ float g_gp  [1u << 23];     // split-K partials (32 MB)

// ===================== HMMA GEMM (bf16 3-split) ===========================
// part[kz][s][n] = sum_{k in slice} W[n][k] * X[s][k]
// 256 thr = 8 warps x 16 weight-rows (NTILE=128). Whole X k-slice staged once;
// mainloop sync-free: LDG W -> pack -> ldmatrix -> 12 HMMA per k16.
#define XPAD 264   // bf16 row stride 528B: ldmatrix conflict-free, Kper<=256

__global__ void __launch_bounds__(256) k_hmma(
    const float* __restrict__ W, const float* __restrict__ X,
    float* __restrict__ part, int N, int K, int Kper)
{
    __shared__ __align__(16) __nv_bfloat16 xhi[SEQ][XPAD];
    __shared__ __align__(16) __nv_bfloat16 xlo[SEQ][XPAD];
    const int tid  = threadIdx.x;
    const int lane = tid & 31;
    const int wid  = tid >> 5;
    const int g    = lane >> 2;
    const int tig  = lane & 3;
    const int nb   = blockIdx.x * 128;
    const int kbeg = blockIdx.y * Kper;

    // ---- stage entire X k-slice (32 x Kper fp32 -> bf16 hi/lo) ----
    const int nf4 = Kper >> 2;   // float4 per token row
    for (int f = tid; f < SEQ * nf4; f += 256) {
        int s = f / nf4, c = f - s * nf4;
        float4 v = *(const float4*)(X + (size_t)s * K + kbeg + c * 4);
        uint2 h = make_uint2(pack_hi(v.x, v.y), pack_hi(v.z, v.w));
        uint2 l = make_uint2(pack_lo(v.x, v.y), pack_lo(v.z, v.w));
        *(uint2*)&xhi[s][c * 4] = h;
        *(uint2*)&xlo[s][c * 4] = l;
    }
    __syncthreads();

    const float* wr0 = W + (size_t)(nb + wid * 16 + g) * K + kbeg;
    const float* wr1 = wr0 + (size_t)8 * K;

    float acc[4][4];
#pragma unroll
    for (int t = 0; t < 4; t++)
#pragma unroll
        for (int r = 0; r < 4; r++) acc[t][r] = 0.f;

    const uint32_t lrow_hi = smem_to_u32(&xhi[0][0]) + lane * (XPAD * 2);
    const uint32_t lrow_lo = smem_to_u32(&xlo[0][0]) + lane * (XPAD * 2);

#pragma unroll 4
    for (int kk = 0; kk < Kper; kk += 16) {
        // W fragment: 4x LDG.64, convert in regs (no smem for W)
        float2 w00 = *(const float2*)(wr0 + kk + 2 * tig);
        float2 w10 = *(const float2*)(wr1 + kk + 2 * tig);
        float2 w01 = *(const float2*)(wr0 + kk + 8 + 2 * tig);
        float2 w11 = *(const float2*)(wr1 + kk + 8 + 2 * tig);
        uint32_t ah[4], al[4];
        ah[0] = pack_hi(w00.x, w00.y); al[0] = pack_lo(w00.x, w00.y);
        ah[1] = pack_hi(w10.x, w10.y); al[1] = pack_lo(w10.x, w10.y);
        ah[2] = pack_hi(w01.x, w01.y); al[2] = pack_lo(w01.x, w01.y);
        ah[3] = pack_hi(w11.x, w11.y); al[3] = pack_lo(w11.x, w11.y);
        uint32_t bh0[4], bh1[4], bl0[4], bl1[4];
        LDSM4(bh0, lrow_hi + kk * 2);
        LDSM4(bh1, lrow_hi + kk * 2 + 16);
        LDSM4(bl0, lrow_lo + kk * 2);
        LDSM4(bl1, lrow_lo + kk * 2 + 16);
#pragma unroll
        for (int t = 0; t < 4; t++) {
            MMA16816(acc[t], ah, bh0[t], bh1[t]);   // hi*hi
            MMA16816(acc[t], ah, bl0[t], bl1[t]);   // hi*lo
            MMA16816(acc[t], al, bh0[t], bh1[t]);   // lo*hi
        }
    }
    // epilogue: D rows = weight n, cols = token s -> part[(kz*32+s)*N+n]
    float* pb = part + (size_t)blockIdx.y * SEQ * N;
    const int n0 = nb + wid * 16 + g;
#pragma unroll
    for (int t = 0; t < 4; t++) {
        int s0 = t * 8 + 2 * tig;
        pb[(size_t)s0 * N + n0]           = acc[t][0];
        pb[(size_t)(s0 + 1) * N + n0]     = acc[t][1];
        pb[(size_t)s0 * N + n0 + 8]       = acc[t][2];
        pb[(size_t)(s0 + 1) * N + n0 + 8] = acc[t][3];
    }
}

// ---- split-K reduce, float4 (+bias, opt exact gelu), token-major ---------
__global__ void k_red4(const float4* __restrict__ part, const float4* __restrict__ bias,
                       float4* __restrict__ out, int N4, int kspl, int act)
{
    int idx = blockIdx.x * 256 + threadIdx.x;   // float4 index over s*N4
    if (idx >= N4 * SEQ) return;
    int n = idx % N4;
    float4 v = bias[n];
    for (int z = 0; z < kspl; z++) {
        float4 p = part[(size_t)z * SEQ * N4 + idx];
        v.x += p.x; v.y += p.y; v.z += p.z; v.w += p.w;
    }
    if (act) {
        v.x *= normcdff(v.x); v.y *= normcdff(v.y);
        v.z *= normcdff(v.z); v.w *= normcdff(v.w);
    }
    out[idx] = v;
}

// ---- scalar split-K reduce (unaligned output: proj head) -----------------
__global__ void k_red_s(const float* __restrict__ part, const float* __restrict__ bias,
                        float* __restrict__ out, int N, int kspl)
{
    int idx = blockIdx.x * 256 + threadIdx.x;
    if (idx >= N * SEQ) return;
    int n = idx % N;
    float v = bias[n];
    for (int z = 0; z < kspl; z++) v += part[(size_t)z * SEQ * N + idx];
    out[idx] = v;
}

// ---- fused split-K reduce + residual + LayerNorm (N=2048), 1 block/token
__global__ void __launch_bounds__(256) k_red_ln(
    const float4* __restrict__ part, const float4* __restrict__ bias,
    float4* __restrict__ x, const float4* __restrict__ g, const float4* __restrict__ b,
    int kspl)
{
    __shared__ float ssum[8], ssq[8], smr[2];
    const int s = blockIdx.x, t = threadIdx.x;
    float4 z[2];
    float ls = 0.f, lq = 0.f;
#pragma unroll
    for (int j = 0; j < 2; j++) {
        int n4 = t + j * 256;                 // 0..511
        size_t base = (size_t)s * 512 + n4;
        float4 v = bias[n4];
        for (int kz = 0; kz < kspl; kz++) {
            float4 p = part[(size_t)kz * SEQ * 512 + base];
            v.x += p.x; v.y += p.y; v.z += p.z; v.w += p.w;
        }
        float4 xx = x[base];
        float4 zz = make_float4(xx.x + v.x, xx.y + v.y, xx.z + v.z, xx.w + v.w);
        z[j] = zz;
        ls += zz.x + zz.y + zz.z + zz.w;
        lq += zz.x * zz.x + zz.y * zz.y + zz.z * zz.z + zz.w * zz.w;
    }
#pragma unroll
    for (int o = 16; o; o >>= 1) { ls += __shfl_xor_sync(~0u, ls, o); lq += __shfl_xor_sync(~0u, lq, o); }
    if ((t & 31) == 0) { ssum[t >> 5] = ls; ssq[t >> 5] = lq; }
    __syncthreads();
    if (t == 0) {
        float a = 0.f, q = 0.f;
#pragma unroll
        for (int w = 0; w < 8; w++) { a += ssum[w]; q += ssq[w]; }
        float m = a * (1.0f / HD);
        smr[0] = m;
        smr[1] = rsqrtf(q * (1.0f / HD) - m * m + 1e-5f);
    }
    __syncthreads();
    float m = smr[0], r = smr[1];
#pragma unroll
    for (int j = 0; j < 2; j++) {
        int n4 = t + j * 256;
        size_t base = (size_t)s * 512 + n4;
        float4 gg = g[n4], bb = b[n4], zz = z[j];
        x[base] = make_float4((zz.x - m) * r * gg.x + bb.x, (zz.y - m) * r * gg.y + bb.y,
                              (zz.z - m) * r * gg.z + bb.z, (zz.w - m) * r * gg.w + bb.w);
    }
}

// ---- broadcast-vector residual + LayerNorm (cross-attn path) -------------
__global__ void __launch_bounds__(256) k_lnvec(
    float4* __restrict__ x, const float4* __restrict__ add,
    const float4* __restrict__ g, const float4* __restrict__ b)
{
    __shared__ float ssum[8], ssq[8], smr[2];
    const int s = blockIdx.x, t = threadIdx.x;
    float4 z[2];
    float ls = 0.f, lq = 0.f;
#pragma unroll
    for (int j = 0; j < 2; j++) {
        int n4 = t + j * 256;
        size_t base = (size_t)s * 512 + n4;
        float4 xx = x[base], a = add[n4];
        float4 zz = make_float4(xx.x + a.x, xx.y + a.y, xx.z + a.z, xx.w + a.w);
        z[j] = zz;
        ls += zz.x + zz.y + zz.z + zz.w;
        lq += zz.x * zz.x + zz.y * zz.y + zz.z * zz.z + zz.w * zz.w;
    }
#pragma unroll
    for (int o = 16; o; o >>= 1) { ls += __shfl_xor_sync(~0u, ls, o); lq += __shfl_xor_sync(~0u, lq, o); }
    if ((t & 31) == 0) { ssum[t >> 5] = ls; ssq[t >> 5] = lq; }
    __syncthreads();
    if (t == 0) {
        float a = 0.f, q = 0.f;
#pragma unroll
        for (int w = 0; w < 8; w++) { a += ssum[w]; q += ssq[w]; }
        float m = a * (1.0f / HD);
        smr[0] = m;
        smr[1] = rsqrtf(q * (1.0f / HD) - m * m + 1e-5f);
    }
    __syncthreads();
    float m = smr[0], r = smr[1];
#pragma unroll
    for (int j = 0; j < 2; j++) {
        int n4 = t + j * 256;
        size_t base = (size_t)s * 512 + n4;
        float4 gg = g[n4], bb = b[n4], zz = z[j];
        x[base] = make_float4((zz.x - m) * r * gg.x + bb.x, (zz.y - m) * r * gg.y + bb.y,
                              (zz.z - m) * r * gg.z + bb.z, (zz.w - m) * r * gg.w + bb.w);
    }
}

// ---- GEMV (cross-attn collapsed path + size head) ------------------------
__global__ void k_gemv(const float* __restrict__ W, const float* __restrict__ bias,
                       const float* __restrict__ vin, float* __restrict__ vout,
                       int K, int act)
{
    int n    = blockIdx.x * 8 + (threadIdx.x >> 5);
    int lane = threadIdx.x & 31;
    const float* wr = W + (size_t)n * K;
    float s = 0.f;
    for (int k = lane * 4; k < K; k += 128) {
        float4 w = *(const float4*)(wr + k);
        float4 x = *(const float4*)(vin + k);
        s += w.x * x.x + w.y * x.y + w.z * x.z + w.w * x.w;
    }
#pragma unroll
    for (int o = 16; o; o >>= 1) s += __shfl_xor_sync(~0u, s, o);
    if (lane == 0) {
        float v = s + bias[n];
        if (act) v = v * normcdff(v);
        vout[n] = v;
    }
}

// ---- size-predictor: 33 logits + softmax ---------------------------------
__global__ void k_sp2(const float* __restrict__ w2, const float* __restrict__ b2,
                      const float* __restrict__ h1, float* __restrict__ outp)
{
    __shared__ float lg[33];
    int lane = threadIdx.x & 31, wid = threadIdx.x >> 5;
    for (int j = wid; j < 33; j += 8) {
        const float* wr = w2 + (size_t)j * 1024;
        float s = 0.f;
        for (int k = lane * 4; k < 1024; k += 128) {
            float4 w = *(const float4*)(wr + k);
            float4 x = *(const float4*)(h1 + k);
            s += w.x * x.x + w.y * x.y + w.z * x.z + w.w * x.w;
        }
#pragma unroll
        for (int o = 16; o; o >>= 1) s += __shfl_xor_sync(~0u, s, o);
        if (lane == 0) lg[j] = s + b2[j];
    }
    __syncthreads();
    if (threadIdx.x == 0) {
        float m = lg[0];
        for (int j = 1; j < 33; j++) m = fmaxf(m, lg[j]);
        float e[33], se = 0.f;
        for (int j = 0; j < 33; j++) { e[j] = expf(lg[j] - m); se += e[j]; }
        float inv = 1.f / se;
        for (int j = 0; j < 33; j++) outp[j] = e[j] * inv;
    }
}

// ---- embedding (token-major) ---------------------------------------------
__global__ void k_embed(const int* __restrict__ tb, const float* __restrict__ bemb,
                        const float* __restrict__ pemb, float* __restrict__ x)
{
    int idx = blockIdx.x * 256 + threadIdx.x;   // s*H + k
    int s = idx >> 11;
    int k = idx & 2047;
    int d = (s == 0) ? 256 : tb[s - 1];
    x[idx] = bemb[(size_t)d * HD + k] + pemb[idx];
}

// ---- self-attention, token-major, one block per head ---------------------
__global__ void __launch_bounds__(256) k_attn(const float* __restrict__ qkv,
                                              float* __restrict__ o)
{
    __shared__ float qs[32][129], ks[32][129], sc[32][33];
    const int h = blockIdx.x, t = threadIdx.x;
    float p0 = 0, p1 = 0, p2 = 0, p3 = 0;

    for (int dc = 0; dc < 256; dc += 128) {
        __syncthreads();
#pragma unroll
        for (int i = 0; i < 16; i++) {
            int idx = t + i * 256;
            int s = idx >> 7, d = idx & 127;
            qs[s][d] = qkv[s * 6144 + h * 256 + dc + d];
            ks[s][d] = qkv[s * 6144 + 2048 + h * 256 + dc + d];
        }
        __syncthreads();
        int qi = t >> 5, ki = t & 31;
        for (int d = 0; d < 128; d++) {
            float kv = ks[ki][d];
            p0 += qs[qi     ][d] * kv;
            p1 += qs[qi +  8][d] * kv;
            p2 += qs[qi + 16][d] * kv;
            p3 += qs[qi + 24][d] * kv;
        }
    }
    {
        int qi = t >> 5, ki = t & 31;
        sc[qi     ][ki] = p0 * 0.0625f;
        sc[qi +  8][ki] = p1 * 0.0625f;
        sc[qi + 16][ki] = p2 * 0.0625f;
        sc[qi + 24][ki] = p3 * 0.0625f;
    }
    __syncthreads();
    {
        int wid = t >> 5, lane = t & 31;
        for (int qi = wid; qi < 32; qi += 8) {
            float v = sc[qi][lane];
            float m = v;
#pragma unroll
            for (int off = 16; off; off >>= 1) m = fmaxf(m, __shfl_xor_sync(~0u, m, off));
            float e = expf(v - m);
            float ss = e;
#pragma unroll
            for (int off = 16; off; off >>= 1) ss += __shfl_xor_sync(~0u, ss, off);
            sc[qi][lane] = e / ss;
        }
    }
    for (int dc = 0; dc < 256; dc += 128) {
        __syncthreads();
#pragma unroll
        for (int i = 0; i < 16; i++) {
            int idx = t + i * 256;
            int s = idx >> 7, d = idx & 127;
            qs[s][d] = qkv[s * 6144 + 4096 + h * 256 + dc + d];
        }
        __syncthreads();
#pragma unroll
        for (int i = 0; i < 16; i++) {
            int idx = t + i * 256;
            int s = idx >> 7, d = idx & 127;
            float a = 0.f;
#pragma unroll
            for (int ki = 0; ki < 32; ki++) a += sc[s][ki] * qs[ki][d];
            o[s * HD + h * 256 + dc + d] = a;
        }
    }
}

// ===================== host orchestration =================================
static void run_hmma(const float* W, const float* X, float* gp, int N, int K, int kz)
{
    dim3 grid(N / 128, kz);
    k_hmma<<<grid, 256>>>(W, X, gp, N, K, K / kz);
}

extern "C" void kernel_launch(void* const* d_in, const int* in_sizes, int n_in,
                              void* d_out, int out_size)
{
    const float* pe      = (const float*)d_in[0];
    const int*   tb      = (const int*)  d_in[1];
    const float* sp_w1   = (const float*)d_in[2];
    const float* sp_b1   = (const float*)d_in[3];
    const float* sp_w2   = (const float*)d_in[4];
    const float* sp_b2   = (const float*)d_in[5];
    const float* bemb    = (const float*)d_in[6];
    const float* pemb    = (const float*)d_in[7];
    const float* proj_w  = (const float*)d_in[8];
    const float* proj_b  = (const float*)d_in[9];
    const float* sa_in_w = (const float*)d_in[10];
    const float* sa_in_b = (const float*)d_in[11];
    const float* sa_out_w= (const float*)d_in[12];
    const float* sa_out_b= (const float*)d_in[13];
    const float* ca_in_w = (const float*)d_in[14];
    const float* ca_in_b = (const float*)d_in[15];
    const float* ca_out_w= (const float*)d_in[16];
    const float* ca_out_b= (const float*)d_in[17];
    const float* ff_w1   = (const float*)d_in[18];
    const float* ff_b1   = (const float*)d_in[19];
    const float* ff_w2   = (const float*)d_in[20];
    const float* ff_b2   = (const float*)d_in[21];
    const float* ln1_g   = (const float*)d_in[22];
    const float* ln1_b   = (const float*)d_in[23];
    const float* ln2_g   = (const float*)d_in[24];
    const float* ln2_b   = (const float*)d_in[25];
    const float* ln3_g   = (const float*)d_in[26];
    const float* ln3_b   = (const float*)d_in[27];
    float* out = (float*)d_out;

    float *xp, *qkvp, *t8, *t2, *vc, *cc, *h1, *gp;
    cudaGetSymbolAddress((void**)&xp,   g_x);
    cudaGetSymbolAddress((void**)&qkvp, g_qkv);
    cudaGetSymbolAddress((void**)&t8,   g_t8);
    cudaGetSymbolAddress((void**)&t2,   g_t2);
    cudaGetSymbolAddress((void**)&vc,   g_vc);
    cudaGetSymbolAddress((void**)&cc,   g_cc);
    cudaGetSymbolAddress((void**)&h1,   g_h1);
    cudaGetSymbolAddress((void**)&gp,   g_gp);

    // size-predictor head -> out[0:33]
    k_gemv<<<1024 / 8, 256>>>(sp_w1, sp_b1, pe, h1, HD, 1);
    k_sp2 <<<1, 256>>>(sp_w2, sp_b2, h1, out);

    // byte+pos embedding -> x (token-major)
    k_embed<<<(SEQ * HD) / 256, 256>>>(tb, bemb, pemb, xp);

    for (int i = 0; i < 3; i++) {
        const float* saw  = sa_in_w  + (size_t)i * 6144 * HD;
        const float* sab  = sa_in_b  + (size_t)i * 6144;
        const float* sow  = sa_out_w + (size_t)i * HD * HD;
        const float* sob  = sa_out_b + (size_t)i * HD;
        const float* cawv = ca_in_w  + (size_t)i * 6144 * HD + (size_t)4096 * HD; // Wv only
        const float* cabv = ca_in_b  + (size_t)i * 6144 + 4096;
        const float* cow  = ca_out_w + (size_t)i * HD * HD;
        const float* cob  = ca_out_b + (size_t)i * HD;
        const float* f1w  = ff_w1 + (size_t)i * 8192 * HD;
        const float* f1b  = ff_b1 + (size_t)i * 8192;
        const float* f2w  = ff_w2 + (size_t)i * HD * 8192;
        const float* f2b  = ff_b2 + (size_t)i * HD;

        // --- self-attention ---
        run_hmma(saw, xp, gp, 6144, HD, 8);                               // 384 blocks, Kper=256
        k_red4<<<(6144 * SEQ / 4 + 255) / 256, 256>>>((const float4*)gp, (const float4*)sab,
                                                      (float4*)qkvp, 6144 / 4, 8, 0);
        k_attn<<<8, 256>>>(qkvp, t2);
        run_hmma(sow, t2, gp, HD, HD, 16);                                // 256 blocks, Kper=128
        k_red_ln<<<SEQ, 256>>>((const float4*)gp, (const float4*)sob, (float4*)xp,
                               (const float4*)(ln1_g + i * HD), (const float4*)(ln1_b + i * HD), 16);

        // --- cross-attention (1 key -> softmax == 1; only Wv, Wout matter) ---
        k_gemv<<<HD / 8, 256>>>(cawv, cabv, pe, vc, HD, 0);
        k_gemv<<<HD / 8, 256>>>(cow,  cob,  vc, cc, HD, 0);
        k_lnvec<<<SEQ, 256>>>((float4*)xp, (const float4*)cc,
                              (const float4*)(ln2_g + i * HD), (const float4*)(ln2_b + i * HD));

        // --- feed-forward ---
        run_hmma(f1w, xp, gp, 8192, HD, 8);                               // 512 blocks, Kper=256
        k_red4<<<(8192 * SEQ / 4 + 255) / 256, 256>>>((const float4*)gp, (const float4*)f1b,
                                                      (float4*)t8, 8192 / 4, 8, 1);
        run_hmma(f2w, t8, gp, HD, 8192, 32);                              // 512 blocks, Kper=256
        k_red_ln<<<SEQ, 256>>>((const float4*)gp, (const float4*)f2b, (float4*)xp,
                               (const float4*)(ln3_g + i * HD), (const float4*)(ln3_b + i * HD), 32);
    }

    // byte logits -> out[33:], row-major [s][256]
    run_hmma(proj_w, xp, gp, 256, HD, 64);                                // 128 blocks, Kper=32
    k_red_s<<<(256 * SEQ + 255) / 256, 256>>>(gp, proj_b, out + 33, 256, 64);
}

// round 9
// speedup vs baseline: 1.8695x; 1.0876x over previous
#include <cuda_runtime.h>
#include <cuda_bf16.h>
#include <cstdint>

#define SEQ 32
#define HD  2048

__device__ __forceinline__ uint32_t smem_to_u32(const void* p) {
    uint32_t a;
    asm("{ .reg .u64 t; cvta.to.shared.u64 t, %1; cvt.u32.u64 %0, t; }" : "=r"(a) : "l"(p));
    return a;
}

#define LDSM4(r, addr) \
    asm volatile("ldmatrix.sync.aligned.m8n8.x4.shared.b16 {%0,%1,%2,%3}, [%4];" \
        : "=r"((r)[0]), "=r"((r)[1]), "=r"((r)[2]), "=r"((r)[3]) : "r"(addr))

#define MMA16816(d, a, b0, b1) \
    asm volatile("mma.sync.aligned.m16n8k16.row.col.f32.bf16.bf16.f32 " \
        "{%0,%1,%2,%3},{%4,%5,%6,%7},{%8,%9},{%0,%1,%2,%3};" \
        : "+f"((d)[0]), "+f"((d)[1]), "+f"((d)[2]), "+f"((d)[3]) \
        : "r"((a)[0]), "r"((a)[1]), "r"((a)[2]), "r"((a)[3]), "r"(b0), "r"(b1))

// hi = top-16-bit truncation packed as bf16x2 (lane0 = first elem)
__device__ __forceinline__ uint32_t pack_hi(float x, float y) {
    return __byte_perm(__float_as_uint(x), __float_as_uint(y), 0x7632);
}
// lo = exact residual vs truncated hi, rn-packed to bf16x2
__device__ __forceinline__ uint32_t pack_lo(float x, float y) {
    float lx = x - __uint_as_float(__float_as_uint(x) & 0xFFFF0000u);
    float ly = y - __uint_as_float(__float_as_uint(y) & 0xFFFF0000u);
    __nv_bfloat162 b = __floats2bfloat162_rn(lx, ly);
    return *reinterpret_cast<uint32_t*>(&b);
}

// ===================== scratch (device globals) ===========================
__device__ float g_x   [SEQ * HD];     // residual, token-major [s][k]
__device__ float g_qkv [SEQ * 6144];
__device__ float g_t8  [SEQ * 8192];
__device__ float g_t2  [SEQ * HD];
__device__ float g_vc  [3 * HD];       // per-layer cross-attn value vec
__device__ float g_cc  [3 * HD];       // per-layer cross-attn output vec
__device__ float g_h1  [1024];
__device__ float g_gp  [1u << 23];     // split-K partials (32 MB)

// ===================== HMMA GEMM (bf16 3-split) ===========================
// part[kz][s][n] = sum_{k in slice} W[n][k] * X[s][k]
// 256 thr = 8 warps x 16 weight-rows (NTILE=128). Whole X k-slice staged once;
// mainloop sync-free: LDG W -> pack -> ldmatrix -> 12 HMMA per k16.
#define XPAD 264   // bf16 row stride 528B: ldmatrix conflict-free, Kper<=256

__global__ void __launch_bounds__(256, 4) k_hmma(
    const float* __restrict__ W, const float* __restrict__ X,
    float* __restrict__ part, int N, int K, int Kper)
{
    __shared__ __align__(16) __nv_bfloat16 xhi[SEQ][XPAD];
    __shared__ __align__(16) __nv_bfloat16 xlo[SEQ][XPAD];
    const int tid  = threadIdx.x;
    const int lane = tid & 31;
    const int wid  = tid >> 5;
    const int g    = lane >> 2;
    const int tig  = lane & 3;
    const int nb   = blockIdx.x * 128;
    const int kbeg = blockIdx.y * Kper;

    // ---- stage entire X k-slice (32 x Kper fp32 -> bf16 hi/lo) ----
    const int nf4 = Kper >> 2;   // float4 per token row
    for (int f = tid; f < SEQ * nf4; f += 256) {
        int s = f / nf4, c = f - s * nf4;
        float4 v = *(const float4*)(X + (size_t)s * K + kbeg + c * 4);
        uint2 h = make_uint2(pack_hi(v.x, v.y), pack_hi(v.z, v.w));
        uint2 l = make_uint2(pack_lo(v.x, v.y), pack_lo(v.z, v.w));
        *(uint2*)&xhi[s][c * 4] = h;
        *(uint2*)&xlo[s][c * 4] = l;
    }
    __syncthreads();

    const float* wr0 = W + (size_t)(nb + wid * 16 + g) * K + kbeg;
    const float* wr1 = wr0 + (size_t)8 * K;

    float acc[4][4];
#pragma unroll
    for (int t = 0; t < 4; t++)
#pragma unroll
        for (int r = 0; r < 4; r++) acc[t][r] = 0.f;

    const uint32_t lrow_hi = smem_to_u32(&xhi[0][0]) + lane * (XPAD * 2);
    const uint32_t lrow_lo = smem_to_u32(&xlo[0][0]) + lane * (XPAD * 2);

#pragma unroll 4
    for (int kk = 0; kk < Kper; kk += 16) {
        // W fragment: 4x LDG.64, convert in regs (no smem for W)
        float2 w00 = *(const float2*)(wr0 + kk + 2 * tig);
        float2 w10 = *(const float2*)(wr1 + kk + 2 * tig);
        float2 w01 = *(const float2*)(wr0 + kk + 8 + 2 * tig);
        float2 w11 = *(const float2*)(wr1 + kk + 8 + 2 * tig);
        uint32_t ah[4], al[4];
        ah[0] = pack_hi(w00.x, w00.y); al[0] = pack_lo(w00.x, w00.y);
        ah[1] = pack_hi(w10.x, w10.y); al[1] = pack_lo(w10.x, w10.y);
        ah[2] = pack_hi(w01.x, w01.y); al[2] = pack_lo(w01.x, w01.y);
        ah[3] = pack_hi(w11.x, w11.y); al[3] = pack_lo(w11.x, w11.y);
        uint32_t bh0[4], bh1[4], bl0[4], bl1[4];
        LDSM4(bh0, lrow_hi + kk * 2);
        LDSM4(bh1, lrow_hi + kk * 2 + 16);
        LDSM4(bl0, lrow_lo + kk * 2);
        LDSM4(bl1, lrow_lo + kk * 2 + 16);
#pragma unroll
        for (int t = 0; t < 4; t++) {
            MMA16816(acc[t], ah, bh0[t], bh1[t]);   // hi*hi
            MMA16816(acc[t], ah, bl0[t], bl1[t]);   // hi*lo
            MMA16816(acc[t], al, bh0[t], bh1[t]);   // lo*hi
        }
    }
    // epilogue: D rows = weight n, cols = token s -> part[(kz*32+s)*N+n]
    float* pb = part + (size_t)blockIdx.y * SEQ * N;
    const int n0 = nb + wid * 16 + g;
#pragma unroll
    for (int t = 0; t < 4; t++) {
        int s0 = t * 8 + 2 * tig;
        pb[(size_t)s0 * N + n0]           = acc[t][0];
        pb[(size_t)(s0 + 1) * N + n0]     = acc[t][1];
        pb[(size_t)s0 * N + n0 + 8]       = acc[t][2];
        pb[(size_t)(s0 + 1) * N + n0 + 8] = acc[t][3];
    }
}

// ---- split-K reduce, float4 (+bias, opt exact gelu), token-major ---------
__global__ void k_red4(const float4* __restrict__ part, const float4* __restrict__ bias,
                       float4* __restrict__ out, int N4, int kspl, int act)
{
    int idx = blockIdx.x * 256 + threadIdx.x;   // float4 index over s*N4
    if (idx >= N4 * SEQ) return;
    int n = idx % N4;
    float4 v = bias[n];
    for (int z = 0; z < kspl; z++) {
        float4 p = part[(size_t)z * SEQ * N4 + idx];
        v.x += p.x; v.y += p.y; v.z += p.z; v.w += p.w;
    }
    if (act) {
        v.x *= normcdff(v.x); v.y *= normcdff(v.y);
        v.z *= normcdff(v.z); v.w *= normcdff(v.w);
    }
    out[idx] = v;
}

// ---- scalar split-K reduce (unaligned output: proj head) -----------------
__global__ void k_red_s(const float* __restrict__ part, const float* __restrict__ bias,
                        float* __restrict__ out, int N, int kspl)
{
    int idx = blockIdx.x * 256 + threadIdx.x;
    if (idx >= N * SEQ) return;
    int n = idx % N;
    float v = bias[n];
    for (int z = 0; z < kspl; z++) v += part[(size_t)z * SEQ * N + idx];
    out[idx] = v;
}

// ---- fused split-K reduce + residual + LayerNorm (N=2048), 1 block/token
__global__ void __launch_bounds__(256) k_red_ln(
    const float4* __restrict__ part, const float4* __restrict__ bias,
    float4* __restrict__ x, const float4* __restrict__ g, const float4* __restrict__ b,
    int kspl)
{
    __shared__ float ssum[8], ssq[8], smr[2];
    const int s = blockIdx.x, t = threadIdx.x;
    float4 z[2];
    float ls = 0.f, lq = 0.f;
#pragma unroll
    for (int j = 0; j < 2; j++) {
        int n4 = t + j * 256;                 // 0..511
        size_t base = (size_t)s * 512 + n4;
        float4 v = bias[n4];
        for (int kz = 0; kz < kspl; kz++) {
            float4 p = part[(size_t)kz * SEQ * 512 + base];
            v.x += p.x; v.y += p.y; v.z += p.z; v.w += p.w;
        }
        float4 xx = x[base];
        float4 zz = make_float4(xx.x + v.x, xx.y + v.y, xx.z + v.z, xx.w + v.w);
        z[j] = zz;
        ls += zz.x + zz.y + zz.z + zz.w;
        lq += zz.x * zz.x + zz.y * zz.y + zz.z * zz.z + zz.w * zz.w;
    }
#pragma unroll
    for (int o = 16; o; o >>= 1) { ls += __shfl_xor_sync(~0u, ls, o); lq += __shfl_xor_sync(~0u, lq, o); }
    if ((t & 31) == 0) { ssum[t >> 5] = ls; ssq[t >> 5] = lq; }
    __syncthreads();
    if (t == 0) {
        float a = 0.f, q = 0.f;
#pragma unroll
        for (int w = 0; w < 8; w++) { a += ssum[w]; q += ssq[w]; }
        float m = a * (1.0f / HD);
        smr[0] = m;
        smr[1] = rsqrtf(q * (1.0f / HD) - m * m + 1e-5f);
    }
    __syncthreads();
    float m = smr[0], r = smr[1];
#pragma unroll
    for (int j = 0; j < 2; j++) {
        int n4 = t + j * 256;
        size_t base = (size_t)s * 512 + n4;
        float4 gg = g[n4], bb = b[n4], zz = z[j];
        x[base] = make_float4((zz.x - m) * r * gg.x + bb.x, (zz.y - m) * r * gg.y + bb.y,
                              (zz.z - m) * r * gg.z + bb.z, (zz.w - m) * r * gg.w + bb.w);
    }
}

// ---- broadcast-vector residual + LayerNorm (cross-attn path) -------------
__global__ void __launch_bounds__(256) k_lnvec(
    float4* __restrict__ x, const float4* __restrict__ add,
    const float4* __restrict__ g, const float4* __restrict__ b)
{
    __shared__ float ssum[8], ssq[8], smr[2];
    const int s = blockIdx.x, t = threadIdx.x;
    float4 z[2];
    float ls = 0.f, lq = 0.f;
#pragma unroll
    for (int j = 0; j < 2; j++) {
        int n4 = t + j * 256;
        size_t base = (size_t)s * 512 + n4;
        float4 xx = x[base], a = add[n4];
        float4 zz = make_float4(xx.x + a.x, xx.y + a.y, xx.z + a.z, xx.w + a.w);
        z[j] = zz;
        ls += zz.x + zz.y + zz.z + zz.w;
        lq += zz.x * zz.x + zz.y * zz.y + zz.z * zz.z + zz.w * zz.w;
    }
#pragma unroll
    for (int o = 16; o; o >>= 1) { ls += __shfl_xor_sync(~0u, ls, o); lq += __shfl_xor_sync(~0u, lq, o); }
    if ((t & 31) == 0) { ssum[t >> 5] = ls; ssq[t >> 5] = lq; }
    __syncthreads();
    if (t == 0) {
        float a = 0.f, q = 0.f;
#pragma unroll
        for (int w = 0; w < 8; w++) { a += ssum[w]; q += ssq[w]; }
        float m = a * (1.0f / HD);
        smr[0] = m;
        smr[1] = rsqrtf(q * (1.0f / HD) - m * m + 1e-5f);
    }
    __syncthreads();
    float m = smr[0], r = smr[1];
#pragma unroll
    for (int j = 0; j < 2; j++) {
        int n4 = t + j * 256;
        size_t base = (size_t)s * 512 + n4;
        float4 gg = g[n4], bb = b[n4], zz = z[j];
        x[base] = make_float4((zz.x - m) * r * gg.x + bb.x, (zz.y - m) * r * gg.y + bb.y,
                              (zz.z - m) * r * gg.z + bb.z, (zz.w - m) * r * gg.w + bb.w);
    }
}

// ---- batched GEMV over layers: vout[l][n] = W_l[n,:].vin_l + b_l[n] ------
// grid (N/8, L); W stride ws (elements), bias stride bs, vin stride vs, vout stride os
__global__ void k_gemv3(const float* __restrict__ W, size_t ws,
                        const float* __restrict__ bias, size_t bs,
                        const float* __restrict__ vin, size_t vs,
                        float* __restrict__ vout, size_t os, int K)
{
    int l    = blockIdx.y;
    int n    = blockIdx.x * 8 + (threadIdx.x >> 5);
    int lane = threadIdx.x & 31;
    const float* wr = W + l * ws + (size_t)n * K;
    const float* vi = vin + l * vs;
    float s = 0.f;
    for (int k = lane * 4; k < K; k += 128) {
        float4 w = *(const float4*)(wr + k);
        float4 x = *(const float4*)(vi + k);
        s += w.x * x.x + w.y * x.y + w.z * x.z + w.w * x.w;
    }
#pragma unroll
    for (int o = 16; o; o >>= 1) s += __shfl_xor_sync(~0u, s, o);
    if (lane == 0) vout[l * os + n] = s + bias[l * bs + n];
}

// ---- GEMV (size head) ----------------------------------------------------
__global__ void k_gemv(const float* __restrict__ W, const float* __restrict__ bias,
                       const float* __restrict__ vin, float* __restrict__ vout,
                       int K, int act)
{
    int n    = blockIdx.x * 8 + (threadIdx.x >> 5);
    int lane = threadIdx.x & 31;
    const float* wr = W + (size_t)n * K;
    float s = 0.f;
    for (int k = lane * 4; k < K; k += 128) {
        float4 w = *(const float4*)(wr + k);
        float4 x = *(const float4*)(vin + k);
        s += w.x * x.x + w.y * x.y + w.z * x.z + w.w * x.w;
    }
#pragma unroll
    for (int o = 16; o; o >>= 1) s += __shfl_xor_sync(~0u, s, o);
    if (lane == 0) {
        float v = s + bias[n];
        if (act) v = v * normcdff(v);
        vout[n] = v;
    }
}

// ---- size-predictor: 33 logits + softmax ---------------------------------
__global__ void k_sp2(const float* __restrict__ w2, const float* __restrict__ b2,
                      const float* __restrict__ h1, float* __restrict__ outp)
{
    __shared__ float lg[33];
    int lane = threadIdx.x & 31, wid = threadIdx.x >> 5;
    for (int j = wid; j < 33; j += 8) {
        const float* wr = w2 + (size_t)j * 1024;
        float s = 0.f;
        for (int k = lane * 4; k < 1024; k += 128) {
            float4 w = *(const float4*)(wr + k);
            float4 x = *(const float4*)(h1 + k);
            s += w.x * x.x + w.y * x.y + w.z * x.z + w.w * x.w;
        }
#pragma unroll
        for (int o = 16; o; o >>= 1) s += __shfl_xor_sync(~0u, s, o);
        if (lane == 0) lg[j] = s + b2[j];
    }
    __syncthreads();
    if (threadIdx.x == 0) {
        float m = lg[0];
        for (int j = 1; j < 33; j++) m = fmaxf(m, lg[j]);
        float e[33], se = 0.f;
        for (int j = 0; j < 33; j++) { e[j] = expf(lg[j] - m); se += e[j]; }
        float inv = 1.f / se;
        for (int j = 0; j < 33; j++) outp[j] = e[j] * inv;
    }
}

// ---- embedding (token-major) ---------------------------------------------
__global__ void k_embed(const int* __restrict__ tb, const float* __restrict__ bemb,
                        const float* __restrict__ pemb, float* __restrict__ x)
{
    int idx = blockIdx.x * 256 + threadIdx.x;   // s*H + k
    int s = idx >> 11;
    int k = idx & 2047;
    int d = (s == 0) ? 256 : tb[s - 1];
    x[idx] = bemb[(size_t)d * HD + k] + pemb[idx];
}

// ---- self-attention, token-major, one block per head ---------------------
__global__ void __launch_bounds__(256) k_attn(const float* __restrict__ qkv,
                                              float* __restrict__ o)
{
    __shared__ float qs[32][129], ks[32][129], sc[32][33];
    const int h = blockIdx.x, t = threadIdx.x;
    float p0 = 0, p1 = 0, p2 = 0, p3 = 0;

    for (int dc = 0; dc < 256; dc += 128) {
        __syncthreads();
#pragma unroll
        for (int i = 0; i < 16; i++) {
            int idx = t + i * 256;
            int s = idx >> 7, d = idx & 127;
            qs[s][d] = qkv[s * 6144 + h * 256 + dc + d];
            ks[s][d] = qkv[s * 6144 + 2048 + h * 256 + dc + d];
        }
        __syncthreads();
        int qi = t >> 5, ki = t & 31;
        for (int d = 0; d < 128; d++) {
            float kv = ks[ki][d];
            p0 += qs[qi     ][d] * kv;
            p1 += qs[qi +  8][d] * kv;
            p2 += qs[qi + 16][d] * kv;
            p3 += qs[qi + 24][d] * kv;
        }
    }
    {
        int qi = t >> 5, ki = t & 31;
        sc[qi     ][ki] = p0 * 0.0625f;
        sc[qi +  8][ki] = p1 * 0.0625f;
        sc[qi + 16][ki] = p2 * 0.0625f;
        sc[qi + 24][ki] = p3 * 0.0625f;
    }
    __syncthreads();
    {
        int wid = t >> 5, lane = t & 31;
        for (int qi = wid; qi < 32; qi += 8) {
            float v = sc[qi][lane];
            float m = v;
#pragma unroll
            for (int off = 16; off; off >>= 1) m = fmaxf(m, __shfl_xor_sync(~0u, m, off));
            float e = expf(v - m);
            float ss = e;
#pragma unroll
            for (int off = 16; off; off >>= 1) ss += __shfl_xor_sync(~0u, ss, off);
            sc[qi][lane] = e / ss;
        }
    }
    for (int dc = 0; dc < 256; dc += 128) {
        __syncthreads();
#pragma unroll
        for (int i = 0; i < 16; i++) {
            int idx = t + i * 256;
            int s = idx >> 7, d = idx & 127;
            qs[s][d] = qkv[s * 6144 + 4096 + h * 256 + dc + d];
        }
        __syncthreads();
#pragma unroll
        for (int i = 0; i < 16; i++) {
            int idx = t + i * 256;
            int s = idx >> 7, d = idx & 127;
            float a = 0.f;
#pragma unroll
            for (int ki = 0; ki < 32; ki++) a += sc[s][ki] * qs[ki][d];
            o[s * HD + h * 256 + dc + d] = a;
        }
    }
}

// ===================== host orchestration =================================
static void run_hmma(const float* W, const float* X, float* gp, int N, int K, int kz)
{
    dim3 grid(N / 128, kz);
    k_hmma<<<grid, 256>>>(W, X, gp, N, K, K / kz);
}

extern "C" void kernel_launch(void* const* d_in, const int* in_sizes, int n_in,
                              void* d_out, int out_size)
{
    const float* pe      = (const float*)d_in[0];
    const int*   tb      = (const int*)  d_in[1];
    const float* sp_w1   = (const float*)d_in[2];
    const float* sp_b1   = (const float*)d_in[3];
    const float* sp_w2   = (const float*)d_in[4];
    const float* sp_b2   = (const float*)d_in[5];
    const float* bemb    = (const float*)d_in[6];
    const float* pemb    = (const float*)d_in[7];
    const float* proj_w  = (const float*)d_in[8];
    const float* proj_b  = (const float*)d_in[9];
    const float* sa_in_w = (const float*)d_in[10];
    const float* sa_in_b = (const float*)d_in[11];
    const float* sa_out_w= (const float*)d_in[12];
    const float* sa_out_b= (const float*)d_in[13];
    const float* ca_in_w = (const float*)d_in[14];
    const float* ca_in_b = (const float*)d_in[15];
    const float* ca_out_w= (const float*)d_in[16];
    const float* ca_out_b= (const float*)d_in[17];
    const float* ff_w1   = (const float*)d_in[18];
    const float* ff_b1   = (const float*)d_in[19];
    const float* ff_w2   = (const float*)d_in[20];
    const float* ff_b2   = (const float*)d_in[21];
    const float* ln1_g   = (const float*)d_in[22];
    const float* ln1_b   = (const float*)d_in[23];
    const float* ln2_g   = (const float*)d_in[24];
    const float* ln2_b   = (const float*)d_in[25];
    const float* ln3_g   = (const float*)d_in[26];
    const float* ln3_b   = (const float*)d_in[27];
    float* out = (float*)d_out;

    float *xp, *qkvp, *t8, *t2, *vc, *cc, *h1, *gp;
    cudaGetSymbolAddress((void**)&xp,   g_x);
    cudaGetSymbolAddress((void**)&qkvp, g_qkv);
    cudaGetSymbolAddress((void**)&t8,   g_t8);
    cudaGetSymbolAddress((void**)&t2,   g_t2);
    cudaGetSymbolAddress((void**)&vc,   g_vc);
    cudaGetSymbolAddress((void**)&cc,   g_cc);
    cudaGetSymbolAddress((void**)&h1,   g_h1);
    cudaGetSymbolAddress((void**)&gp,   g_gp);

    // size-predictor head -> out[0:33]
    k_gemv<<<1024 / 8, 256>>>(sp_w1, sp_b1, pe, h1, HD, 1);
    k_sp2 <<<1, 256>>>(sp_w2, sp_b2, h1, out);

    // byte+pos embedding -> x (token-major)
    k_embed<<<(SEQ * HD) / 256, 256>>>(tb, bemb, pemb, xp);

    // cross-attention collapsed path, all 3 layers batched (depends only on pe):
    // vc[l] = Wv_l . pe + bv_l ; cc[l] = Wout_l . vc[l] + bout_l
    {
        dim3 gv(HD / 8, 3);
        k_gemv3<<<gv, 256>>>(ca_in_w + (size_t)4096 * HD, (size_t)6144 * HD,
                             ca_in_b + 4096, 6144, pe, 0, vc, HD, HD);
        k_gemv3<<<gv, 256>>>(ca_out_w, (size_t)HD * HD,
                             ca_out_b, HD, vc, HD, cc, HD, HD);
    }

    for (int i = 0; i < 3; i++) {
        const float* saw  = sa_in_w  + (size_t)i * 6144 * HD;
        const float* sab  = sa_in_b  + (size_t)i * 6144;
        const float* sow  = sa_out_w + (size_t)i * HD * HD;
        const float* sob  = sa_out_b + (size_t)i * HD;
        const float* f1w  = ff_w1 + (size_t)i * 8192 * HD;
        const float* f1b  = ff_b1 + (size_t)i * 8192;
        const float* f2w  = ff_w2 + (size_t)i * HD * 8192;
        const float* f2b  = ff_b2 + (size_t)i * HD;

        // --- self-attention ---
        run_hmma(saw, xp, gp, 6144, HD, 16);                              // 768 blocks, Kper=128
        k_red4<<<(6144 * SEQ / 4 + 255) / 256, 256>>>((const float4*)gp, (const float4*)sab,
                                                      (float4*)qkvp, 6144 / 4, 16, 0);
        k_attn<<<8, 256>>>(qkvp, t2);
        run_hmma(sow, t2, gp, HD, HD, 32);                                // 512 blocks, Kper=64
        k_red_ln<<<SEQ, 256>>>((const float4*)gp, (const float4*)sob, (float4*)xp,
                               (const float4*)(ln1_g + i * HD), (const float4*)(ln1_b + i * HD), 32);

        // --- cross-attention (1 key -> softmax == 1; precomputed cc) ---
        k_lnvec<<<SEQ, 256>>>((float4*)xp, (const float4*)(cc + i * HD),
                              (const float4*)(ln2_g + i * HD), (const float4*)(ln2_b + i * HD));

        // --- feed-forward ---
        run_hmma(f1w, xp, gp, 8192, HD, 16);                              // 1024 blocks, Kper=128
        k_red4<<<(8192 * SEQ / 4 + 255) / 256, 256>>>((const float4*)gp, (const float4*)f1b,
                                                      (float4*)t8, 8192 / 4, 16, 1);
        run_hmma(f2w, t8, gp, HD, 8192, 64);                              // 1024 blocks, Kper=128
        k_red_ln<<<SEQ, 256>>>((const float4*)gp, (const float4*)f2b, (float4*)xp,
                               (const float4*)(ln3_g + i * HD), (const float4*)(ln3_b + i * HD), 64);
    }

    // byte logits -> out[33:], row-major [s][256]
    run_hmma(proj_w, xp, gp, 256, HD, 64);                                // 128 blocks, Kper=32
    k_red_s<<<(256 * SEQ + 255) / 256, 256>>>(gp, proj_b, out + 33, 256, 64);
}

// round 11
// speedup vs baseline: 1.8791x; 1.0051x over previous
#include <cuda_runtime.h>
#include <cuda_bf16.h>
#include <cstdint>

#define SEQ 32
#define HD  2048

__device__ __forceinline__ uint32_t smem_to_u32(const void* p) {
    uint32_t a;
    asm("{ .reg .u64 t; cvta.to.shared.u64 t, %1; cvt.u32.u64 %0, t; }" : "=r"(a) : "l"(p));
    return a;
}

#define LDSM4(r, addr) \
    asm volatile("ldmatrix.sync.aligned.m8n8.x4.shared.b16 {%0,%1,%2,%3}, [%4];" \
        : "=r"((r)[0]), "=r"((r)[1]), "=r"((r)[2]), "=r"((r)[3]) : "r"(addr))

#define MMA16816(d, a, b0, b1) \
    asm volatile("mma.sync.aligned.m16n8k16.row.col.f32.bf16.bf16.f32 " \
        "{%0,%1,%2,%3},{%4,%5,%6,%7},{%8,%9},{%0,%1,%2,%3};" \
        : "+f"((d)[0]), "+f"((d)[1]), "+f"((d)[2]), "+f"((d)[3]) \
        : "r"((a)[0]), "r"((a)[1]), "r"((a)[2]), "r"((a)[3]), "r"(b0), "r"(b1))

// hi = top-16-bit truncation packed as bf16x2 (lane0 = first elem)
__device__ __forceinline__ uint32_t pack_hi(float x, float y) {
    return __byte_perm(__float_as_uint(x), __float_as_uint(y), 0x7632);
}
// lo = exact residual vs truncated hi, rn-packed to bf16x2
__device__ __forceinline__ uint32_t pack_lo(float x, float y) {
    float lx = x - __uint_as_float(__float_as_uint(x) & 0xFFFF0000u);
    float ly = y - __uint_as_float(__float_as_uint(y) & 0xFFFF0000u);
    __nv_bfloat162 b = __floats2bfloat162_rn(lx, ly);
    return *reinterpret_cast<uint32_t*>(&b);
}

// ===================== scratch (device globals) ===========================
__device__ float g_x   [SEQ * HD];     // residual, token-major [s][k]
__device__ float g_qkv [SEQ * 6144];
__device__ float g_t8  [SEQ * 8192];
__device__ float g_t2  [SEQ * HD];
__device__ float g_vc  [3 * HD];       // per-layer cross-attn value vec
__device__ float g_cc  [3 * HD];       // per-layer cross-attn output vec
__device__ float g_h1  [1024];
__device__ float g_gp  [1u << 23];     // split-K partials (32 MB)

// ===================== HMMA GEMM (bf16 3-split) ===========================
// part[kz][s][n] = sum_{k in slice} W[n][k] * X[s][k]
// 256 thr = 8 warps x 16 weight-rows (NTILE=128). Whole X k-slice staged once.
// k-order is permuted within each 16-element group on BOTH operands so a
// single LDG.128 per row supplies the full A fragment:
//   stored(2i,2i+1)   <- global(4i,4i+1)    [feeds a0/a1 via b0 window]
//   stored(8+2i,+1)   <- global(4i+2,4i+3)  [feeds a2/a3 via b1 window]
#define XPAD 264   // bf16 row stride 528B: ldmatrix conflict-free, Kper<=256

__global__ void __launch_bounds__(256, 4) k_hmma(
    const float* __restrict__ W, const float* __restrict__ X,
    float* __restrict__ part, int N, int K, int Kper)
{
    __shared__ __align__(16) __nv_bfloat16 xhi[SEQ][XPAD];
    __shared__ __align__(16) __nv_bfloat16 xlo[SEQ][XPAD];
    const int tid  = threadIdx.x;
    const int lane = tid & 31;
    const int wid  = tid >> 5;
    const int g    = lane >> 2;
    const int tig  = lane & 3;
    const int nb   = blockIdx.x * 128;
    const int kbeg = blockIdx.y * Kper;

    // ---- stage X k-slice (32 x Kper fp32 -> bf16 hi/lo), permuted k-order
    {
        uint32_t* xh32 = (uint32_t*)&xhi[0][0];
        uint32_t* xl32 = (uint32_t*)&xlo[0][0];
        const int nf4 = Kper >> 2;   // float4 per token row
        for (int f = tid; f < SEQ * nf4; f += 256) {
            int s = f / nf4, c = f - s * nf4;      // c: float4 idx, global k=4c
            int g16 = c >> 2, c4 = c & 3;
            int u0 = s * (XPAD / 2) + g16 * 8 + c4;  // u32 slot for (4c,4c+1)
            float4 v = *(const float4*)(X + (size_t)s * K + kbeg + c * 4);
            xh32[u0]     = pack_hi(v.x, v.y);
            xh32[u0 + 4] = pack_hi(v.z, v.w);
            xl32[u0]     = pack_lo(v.x, v.y);
            xl32[u0 + 4] = pack_lo(v.z, v.w);
        }
    }
    __syncthreads();

    const float* wr0 = W + (size_t)(nb + wid * 16 + g) * K + kbeg + 4 * tig;
    const float* wr1 = wr0 + (size_t)8 * K;

    float acc[4][4];
#pragma unroll
    for (int t = 0; t < 4; t++)
#pragma unroll
        for (int r = 0; r < 4; r++) acc[t][r] = 0.f;

    const uint32_t lrow_hi = smem_to_u32(&xhi[0][0]) + lane * (XPAD * 2);
    const uint32_t lrow_lo = smem_to_u32(&xlo[0][0]) + lane * (XPAD * 2);

#pragma unroll 8
    for (int kk = 0; kk < Kper; kk += 16) {
        // W fragment: 2x LDG.128 (row g, row g+8); permuted k makes this exact
        float4 w0 = *(const float4*)(wr0 + kk);
        float4 w1 = *(const float4*)(wr1 + kk);
        uint32_t ah[4], al[4];
        ah[0] = pack_hi(w0.x, w0.y); al[0] = pack_lo(w0.x, w0.y);
        ah[1] = pack_hi(w1.x, w1.y); al[1] = pack_lo(w1.x, w1.y);
        ah[2] = pack_hi(w0.z, w0.w); al[2] = pack_lo(w0.z, w0.w);
        ah[3] = pack_hi(w1.z, w1.w); al[3] = pack_lo(w1.z, w1.w);
        uint32_t bh0[4], bh1[4], bl0[4], bl1[4];
        LDSM4(bh0, lrow_hi + kk * 2);
        LDSM4(bh1, lrow_hi + kk * 2 + 16);
        LDSM4(bl0, lrow_lo + kk * 2);
        LDSM4(bl1, lrow_lo + kk * 2 + 16);
#pragma unroll
        for (int t = 0; t < 4; t++) {
            MMA16816(acc[t], ah, bh0[t], bh1[t]);   // hi*hi
            MMA16816(acc[t], ah, bl0[t], bl1[t]);   // hi*lo
            MMA16816(acc[t], al, bh0[t], bh1[t]);   // lo*hi
        }
    }
    // epilogue: D rows = weight n, cols = token s -> part[(kz*32+s)*N+n]
    float* pb = part + (size_t)blockIdx.y * SEQ * N;
    const int n0 = nb + wid * 16 + g;
#pragma unroll
    for (int t = 0; t < 4; t++) {
        int s0 = t * 8 + 2 * tig;
        pb[(size_t)s0 * N + n0]           = acc[t][0];
        pb[(size_t)(s0 + 1) * N + n0]     = acc[t][1];
        pb[(size_t)s0 * N + n0 + 8]       = acc[t][2];
        pb[(size_t)(s0 + 1) * N + n0 + 8] = acc[t][3];
    }
}

// ---- split-K reduce, float4 (+bias, opt exact gelu), token-major ---------
__global__ void k_red4(const float4* __restrict__ part, const float4* __restrict__ bias,
                       float4* __restrict__ out, int N4, int kspl, int act)
{
    int idx = blockIdx.x * 256 + threadIdx.x;   // float4 index over s*N4
    if (idx >= N4 * SEQ) return;
    int n = idx % N4;
    float4 v = bias[n];
    for (int z = 0; z < kspl; z++) {
        float4 p = part[(size_t)z * SEQ * N4 + idx];
        v.x += p.x; v.y += p.y; v.z += p.z; v.w += p.w;
    }
    if (act) {
        v.x *= normcdff(v.x); v.y *= normcdff(v.y);
        v.z *= normcdff(v.z); v.w *= normcdff(v.w);
    }
    out[idx] = v;
}

// ---- scalar split-K reduce (unaligned output: proj head) -----------------
__global__ void k_red_s(const float* __restrict__ part, const float* __restrict__ bias,
                        float* __restrict__ out, int N, int kspl)
{
    int idx = blockIdx.x * 256 + threadIdx.x;
    if (idx >= N * SEQ) return;
    int n = idx % N;
    float v = bias[n];
    for (int z = 0; z < kspl; z++) v += part[(size_t)z * SEQ * N + idx];
    out[idx] = v;
}

// ---- fused split-K reduce + residual + LayerNorm (N=2048), 1 block/token
__global__ void __launch_bounds__(256) k_red_ln(
    const float4* __restrict__ part, const float4* __restrict__ bias,
    float4* __restrict__ x, const float4* __restrict__ g, const float4* __restrict__ b,
    int kspl)
{
    __shared__ float ssum[8], ssq[8], smr[2];
    const int s = blockIdx.x, t = threadIdx.x;
    float4 z[2];
    float ls = 0.f, lq = 0.f;
#pragma unroll
    for (int j = 0; j < 2; j++) {
        int n4 = t + j * 256;                 // 0..511
        size_t base = (size_t)s * 512 + n4;
        float4 v = bias[n4];
        for (int kz = 0; kz < kspl; kz++) {
            float4 p = part[(size_t)kz * SEQ * 512 + base];
            v.x += p.x; v.y += p.y; v.z += p.z; v.w += p.w;
        }
        float4 xx = x[base];
        float4 zz = make_float4(xx.x + v.x, xx.y + v.y, xx.z + v.z, xx.w + v.w);
        z[j] = zz;
        ls += zz.x + zz.y + zz.z + zz.w;
        lq += zz.x * zz.x + zz.y * zz.y + zz.z * zz.z + zz.w * zz.w;
    }
#pragma unroll
    for (int o = 16; o; o >>= 1) { ls += __shfl_xor_sync(~0u, ls, o); lq += __shfl_xor_sync(~0u, lq, o); }
    if ((t & 31) == 0) { ssum[t >> 5] = ls; ssq[t >> 5] = lq; }
    __syncthreads();
    if (t == 0) {
        float a = 0.f, q = 0.f;
#pragma unroll
        for (int w = 0; w < 8; w++) { a += ssum[w]; q += ssq[w]; }
        float m = a * (1.0f / HD);
        smr[0] = m;
        smr[1] = rsqrtf(q * (1.0f / HD) - m * m + 1e-5f);
    }
    __syncthreads();
    float m = smr[0], r = smr[1];
#pragma unroll
    for (int j = 0; j < 2; j++) {
        int n4 = t + j * 256;
        size_t base = (size_t)s * 512 + n4;
        float4 gg = g[n4], bb = b[n4], zz = z[j];
        x[base] = make_float4((zz.x - m) * r * gg.x + bb.x, (zz.y - m) * r * gg.y + bb.y,
                              (zz.z - m) * r * gg.z + bb.z, (zz.w - m) * r * gg.w + bb.w);
    }
}

// ---- broadcast-vector residual + LayerNorm (cross-attn path) -------------
__global__ void __launch_bounds__(256) k_lnvec(
    float4* __restrict__ x, const float4* __restrict__ add,
    const float4* __restrict__ g, const float4* __restrict__ b)
{
    __shared__ float ssum[8], ssq[8], smr[2];
    const int s = blockIdx.x, t = threadIdx.x;
    float4 z[2];
    float ls = 0.f, lq = 0.f;
#pragma unroll
    for (int j = 0; j < 2; j++) {
        int n4 = t + j * 256;
        size_t base = (size_t)s * 512 + n4;
        float4 xx = x[base], a = add[n4];
        float4 zz = make_float4(xx.x + a.x, xx.y + a.y, xx.z + a.z, xx.w + a.w);
        z[j] = zz;
        ls += zz.x + zz.y + zz.z + zz.w;
        lq += zz.x * zz.x + zz.y * zz.y + zz.z * zz.z + zz.w * zz.w;
    }
#pragma unroll
    for (int o = 16; o; o >>= 1) { ls += __shfl_xor_sync(~0u, ls, o); lq += __shfl_xor_sync(~0u, lq, o); }
    if ((t & 31) == 0) { ssum[t >> 5] = ls; ssq[t >> 5] = lq; }
    __syncthreads();
    if (t == 0) {
        float a = 0.f, q = 0.f;
#pragma unroll
        for (int w = 0; w < 8; w++) { a += ssum[w]; q += ssq[w]; }
        float m = a * (1.0f / HD);
        smr[0] = m;
        smr[1] = rsqrtf(q * (1.0f / HD) - m * m + 1e-5f);
    }
    __syncthreads();
    float m = smr[0], r = smr[1];
#pragma unroll
    for (int j = 0; j < 2; j++) {
        int n4 = t + j * 256;
        size_t base = (size_t)s * 512 + n4;
        float4 gg = g[n4], bb = b[n4], zz = z[j];
        x[base] = make_float4((zz.x - m) * r * gg.x + bb.x, (zz.y - m) * r * gg.y + bb.y,
                              (zz.z - m) * r * gg.z + bb.z, (zz.w - m) * r * gg.w + bb.w);
    }
}

// ---- batched GEMV over layers: vout[l][n] = W_l[n,:].vin_l + b_l[n] ------
__global__ void k_gemv3(const float* __restrict__ W, size_t ws,
                        const float* __restrict__ bias, size_t bs,
                        const float* __restrict__ vin, size_t vs,
                        float* __restrict__ vout, size_t os, int K)
{
    int l    = blockIdx.y;
    int n    = blockIdx.x * 8 + (threadIdx.x >> 5);
    int lane = threadIdx.x & 31;
    const float* wr = W + l * ws + (size_t)n * K;
    const float* vi = vin + l * vs;
    float s = 0.f;
    for (int k = lane * 4; k < K; k += 128) {
        float4 w = *(const float4*)(wr + k);
        float4 x = *(const float4*)(vi + k);
        s += w.x * x.x + w.y * x.y + w.z * x.z + w.w * x.w;
    }
#pragma unroll
    for (int o = 16; o; o >>= 1) s += __shfl_xor_sync(~0u, s, o);
    if (lane == 0) vout[l * os + n] = s + bias[l * bs + n];
}

// ---- GEMV (size head) ----------------------------------------------------
__global__ void k_gemv(const float* __restrict__ W, const float* __restrict__ bias,
                       const float* __restrict__ vin, float* __restrict__ vout,
                       int K, int act)
{
    int n    = blockIdx.x * 8 + (threadIdx.x >> 5);
    int lane = threadIdx.x & 31;
    const float* wr = W + (size_t)n * K;
    float s = 0.f;
    for (int k = lane * 4; k < K; k += 128) {
        float4 w = *(const float4*)(wr + k);
        float4 x = *(const float4*)(vin + k);
        s += w.x * x.x + w.y * x.y + w.z * x.z + w.w * x.w;
    }
#pragma unroll
    for (int o = 16; o; o >>= 1) s += __shfl_xor_sync(~0u, s, o);
    if (lane == 0) {
        float v = s + bias[n];
        if (act) v = v * normcdff(v);
        vout[n] = v;
    }
}

// ---- size-predictor: 33 logits + softmax ---------------------------------
__global__ void k_sp2(const float* __restrict__ w2, const float* __restrict__ b2,
                      const float* __restrict__ h1, float* __restrict__ outp)
{
    __shared__ float lg[33];
    int lane = threadIdx.x & 31, wid = threadIdx.x >> 5;
    for (int j = wid; j < 33; j += 8) {
        const float* wr = w2 + (size_t)j * 1024;
        float s = 0.f;
        for (int k = lane * 4; k < 1024; k += 128) {
            float4 w = *(const float4*)(wr + k);
            float4 x = *(const float4*)(h1 + k);
            s += w.x * x.x + w.y * x.y + w.z * x.z + w.w * x.w;
        }
#pragma unroll
        for (int o = 16; o; o >>= 1) s += __shfl_xor_sync(~0u, s, o);
        if (lane == 0) lg[j] = s + b2[j];
    }
    __syncthreads();
    if (threadIdx.x == 0) {
        float m = lg[0];
        for (int j = 1; j < 33; j++) m = fmaxf(m, lg[j]);
        float e[33], se = 0.f;
        for (int j = 0; j < 33; j++) { e[j] = expf(lg[j] - m); se += e[j]; }
        float inv = 1.f / se;
        for (int j = 0; j < 33; j++) outp[j] = e[j] * inv;
    }
}

// ---- embedding (token-major) ---------------------------------------------
__global__ void k_embed(const int* __restrict__ tb, const float* __restrict__ bemb,
                        const float* __restrict__ pemb, float* __restrict__ x)
{
    int idx = blockIdx.x * 256 + threadIdx.x;   // s*H + k
    int s = idx >> 11;
    int k = idx & 2047;
    int d = (s == 0) ? 256 : tb[s - 1];
    x[idx] = bemb[(size_t)d * HD + k] + pemb[idx];
}

// ---- self-attention, token-major, one block per head ---------------------
__global__ void __launch_bounds__(256) k_attn(const float* __restrict__ qkv,
                                              float* __restrict__ o)
{
    __shared__ float qs[32][129], ks[32][129], sc[32][33];
    const int h = blockIdx.x, t = threadIdx.x;
    float p0 = 0, p1 = 0, p2 = 0, p3 = 0;

    for (int dc = 0; dc < 256; dc += 128) {
        __syncthreads();
#pragma unroll
        for (int i = 0; i < 16; i++) {
            int idx = t + i * 256;
            int s = idx >> 7, d = idx & 127;
            qs[s][d] = qkv[s * 6144 + h * 256 + dc + d];
            ks[s][d] = qkv[s * 6144 + 2048 + h * 256 + dc + d];
        }
        __syncthreads();
        int qi = t >> 5, ki = t & 31;
        for (int d = 0; d < 128; d++) {
            float kv = ks[ki][d];
            p0 += qs[qi     ][d] * kv;
            p1 += qs[qi +  8][d] * kv;
            p2 += qs[qi + 16][d] * kv;
            p3 += qs[qi + 24][d] * kv;
        }
    }
    {
        int qi = t >> 5, ki = t & 31;
        sc[qi     ][ki] = p0 * 0.0625f;
        sc[qi +  8][ki] = p1 * 0.0625f;
        sc[qi + 16][ki] = p2 * 0.0625f;
        sc[qi + 24][ki] = p3 * 0.0625f;
    }
    __syncthreads();
    {
        int wid = t >> 5, lane = t & 31;
        for (int qi = wid; qi < 32; qi += 8) {
            float v = sc[qi][lane];
            float m = v;
#pragma unroll
            for (int off = 16; off; off >>= 1) m = fmaxf(m, __shfl_xor_sync(~0u, m, off));
            float e = expf(v - m);
            float ss = e;
#pragma unroll
            for (int off = 16; off; off >>= 1) ss += __shfl_xor_sync(~0u, ss, off);
            sc[qi][lane] = e / ss;
        }
    }
    for (int dc = 0; dc < 256; dc += 128) {
        __syncthreads();
#pragma unroll
        for (int i = 0; i < 16; i++) {
            int idx = t + i * 256;
            int s = idx >> 7, d = idx & 127;
            qs[s][d] = qkv[s * 6144 + 4096 + h * 256 + dc + d];
        }
        __syncthreads();
#pragma unroll
        for (int i = 0; i < 16; i++) {
            int idx = t + i * 256;
            int s = idx >> 7, d = idx & 127;
            float a = 0.f;
#pragma unroll
            for (int ki = 0; ki < 32; ki++) a += sc[s][ki] * qs[ki][d];
            o[s * HD + h * 256 + dc + d] = a;
        }
    }
}

// ===================== host orchestration =================================
static void run_hmma(const float* W, const float* X, float* gp, int N, int K, int kz)
{
    dim3 grid(N / 128, kz);
    k_hmma<<<grid, 256>>>(W, X, gp, N, K, K / kz);
}

extern "C" void kernel_launch(void* const* d_in, const int* in_sizes, int n_in,
                              void* d_out, int out_size)
{
    const float* pe      = (const float*)d_in[0];
    const int*   tb      = (const int*)  d_in[1];
    const float* sp_w1   = (const float*)d_in[2];
    const float* sp_b1   = (const float*)d_in[3];
    const float* sp_w2   = (const float*)d_in[4];
    const float* sp_b2   = (const float*)d_in[5];
    const float* bemb    = (const float*)d_in[6];
    const float* pemb    = (const float*)d_in[7];
    const float* proj_w  = (const float*)d_in[8];
    const float* proj_b  = (const float*)d_in[9];
    const float* sa_in_w = (const float*)d_in[10];
    const float* sa_in_b = (const float*)d_in[11];
    const float* sa_out_w= (const float*)d_in[12];
    const float* sa_out_b= (const float*)d_in[13];
    const float* ca_in_w = (const float*)d_in[14];
    const float* ca_in_b = (const float*)d_in[15];
    const float* ca_out_w= (const float*)d_in[16];
    const float* ca_out_b= (const float*)d_in[17];
    const float* ff_w1   = (const float*)d_in[18];
    const float* ff_b1   = (const float*)d_in[19];
    const float* ff_w2   = (const float*)d_in[20];
    const float* ff_b2   = (const float*)d_in[21];
    const float* ln1_g   = (const float*)d_in[22];
    const float* ln1_b   = (const float*)d_in[23];
    const float* ln2_g   = (const float*)d_in[24];
    const float* ln2_b   = (const float*)d_in[25];
    const float* ln3_g   = (const float*)d_in[26];
    const float* ln3_b   = (const float*)d_in[27];
    float* out = (float*)d_out;

    float *xp, *qkvp, *t8, *t2, *vc, *cc, *h1, *gp;
    cudaGetSymbolAddress((void**)&xp,   g_x);
    cudaGetSymbolAddress((void**)&qkvp, g_qkv);
    cudaGetSymbolAddress((void**)&t8,   g_t8);
    cudaGetSymbolAddress((void**)&t2,   g_t2);
    cudaGetSymbolAddress((void**)&vc,   g_vc);
    cudaGetSymbolAddress((void**)&cc,   g_cc);
    cudaGetSymbolAddress((void**)&h1,   g_h1);
    cudaGetSymbolAddress((void**)&gp,   g_gp);

    // size-predictor head -> out[0:33]
    k_gemv<<<1024 / 8, 256>>>(sp_w1, sp_b1, pe, h1, HD, 1);
    k_sp2 <<<1, 256>>>(sp_w2, sp_b2, h1, out);

    // byte+pos embedding -> x (token-major)
    k_embed<<<(SEQ * HD) / 256, 256>>>(tb, bemb, pemb, xp);

    // cross-attention collapsed path, all 3 layers batched (depends only on pe):
    // vc[l] = Wv_l . pe + bv_l ; cc[l] = Wout_l . vc[l] + bout_l
    {
        dim3 gv(HD / 8, 3);
        k_gemv3<<<gv, 256>>>(ca_in_w + (size_t)4096 * HD, (size_t)6144 * HD,
                             ca_in_b + 4096, 6144, pe, 0, vc, HD, HD);
        k_gemv3<<<gv, 256>>>(ca_out_w, (size_t)HD * HD,
                             ca_out_b, HD, vc, HD, cc, HD, HD);
    }

    for (int i = 0; i < 3; i++) {
        const float* saw  = sa_in_w  + (size_t)i * 6144 * HD;
        const float* sab  = sa_in_b  + (size_t)i * 6144;
        const float* sow  = sa_out_w + (size_t)i * HD * HD;
        const float* sob  = sa_out_b + (size_t)i * HD;
        const float* f1w  = ff_w1 + (size_t)i * 8192 * HD;
        const float* f1b  = ff_b1 + (size_t)i * 8192;
        const float* f2w  = ff_w2 + (size_t)i * HD * 8192;
        const float* f2b  = ff_b2 + (size_t)i * HD;

        // --- self-attention ---
        run_hmma(saw, xp, gp, 6144, HD, 16);                              // 768 blocks, Kper=128
        k_red4<<<(6144 * SEQ / 4 + 255) / 256, 256>>>((const float4*)gp, (const float4*)sab,
                                                      (float4*)qkvp, 6144 / 4, 16, 0);
        k_attn<<<8, 256>>>(qkvp, t2);
        run_hmma(sow, t2, gp, HD, HD, 32);                                // 512 blocks, Kper=64
        k_red_ln<<<SEQ, 256>>>((const float4*)gp, (const float4*)sob, (float4*)xp,
                               (const float4*)(ln1_g + i * HD), (const float4*)(ln1_b + i * HD), 32);

        // --- cross-attention (1 key -> softmax == 1; precomputed cc) ---
        k_lnvec<<<SEQ, 256>>>((float4*)xp, (const float4*)(cc + i * HD),
                              (const float4*)(ln2_g + i * HD), (const float4*)(ln2_b + i * HD));

        // --- feed-forward ---
        run_hmma(f1w, xp, gp, 8192, HD, 16);                              // 1024 blocks, Kper=128
        k_red4<<<(8192 * SEQ / 4 + 255) / 256, 256>>>((const float4*)gp, (const float4*)f1b,
                                                      (float4*)t8, 8192 / 4, 16, 1);
        run_hmma(f2w, t8, gp, HD, 8192, 64);                              // 1024 blocks, Kper=128
        k_red_ln<<<SEQ, 256>>>((const float4*)gp, (const float4*)f2b, (float4*)xp,
                               (const float4*)(ln3_g + i * HD), (const float4*)(ln3_b + i * HD), 64);
    }

    // byte logits -> out[33:], row-major [s][256]
    run_hmma(proj_w, xp, gp, 256, HD, 64);                                // 128 blocks, Kper=32
    k_red_s<<<(256 * SEQ + 255) / 256, 256>>>(gp, proj_b, out + 33, 256, 64);
}

// round 12
// speedup vs baseline: 2.0826x; 1.1083x over previous
#include <cuda_runtime.h>
#include <cuda_bf16.h>
#include <cstdint>

#define SEQ 32
#define HD  2048

__device__ __forceinline__ uint32_t smem_to_u32(const void* p) {
    uint32_t a;
    asm("{ .reg .u64 t; cvta.to.shared.u64 t, %1; cvt.u32.u64 %0, t; }" : "=r"(a) : "l"(p));
    return a;
}

#define LDSM4(r, addr) \
    asm volatile("ldmatrix.sync.aligned.m8n8.x4.shared.b16 {%0,%1,%2,%3}, [%4];" \
        : "=r"((r)[0]), "=r"((r)[1]), "=r"((r)[2]), "=r"((r)[3]) : "r"(addr))

#define MMA16816(d, a, b0, b1) \
    asm volatile("mma.sync.aligned.m16n8k16.row.col.f32.bf16.bf16.f32 " \
        "{%0,%1,%2,%3},{%4,%5,%6,%7},{%8,%9},{%0,%1,%2,%3};" \
        : "+f"((d)[0]), "+f"((d)[1]), "+f"((d)[2]), "+f"((d)[3]) \
        : "r"((a)[0]), "r"((a)[1]), "r"((a)[2]), "r"((a)[3]), "r"(b0), "r"(b1))

__device__ __forceinline__ uint32_t pack_hi(float x, float y) {
    return __byte_perm(__float_as_uint(x), __float_as_uint(y), 0x7632);
}
__device__ __forceinline__ uint32_t pack_lo(float x, float y) {
    float lx = x - __uint_as_float(__float_as_uint(x) & 0xFFFF0000u);
    float ly = y - __uint_as_float(__float_as_uint(y) & 0xFFFF0000u);
    __nv_bfloat162 b = __floats2bfloat162_rn(lx, ly);
    return *reinterpret_cast<uint32_t*>(&b);
}

__device__ __forceinline__ void f4acc(float4& a, const float4 b) {
    a.x += b.x; a.y += b.y; a.z += b.z; a.w += b.w;
}

// ===================== scratch (device globals) ===========================
__device__ float g_x   [SEQ * HD];     // residual, token-major [s][k]
__device__ float g_qkv [SEQ * 6144];
__device__ float g_t8  [SEQ * 8192];
__device__ float g_t2  [SEQ * HD];
__device__ float g_vc  [3 * HD];
__device__ float g_cc  [3 * HD];
__device__ float g_h1  [1024];
__device__ float g_gp  [1u << 23];     // split-K partials (32 MB)

// ===================== HMMA GEMM (bf16 3-split) ===========================
// part[kz][s][n] = sum_{k in slice} W[n][k] * X[s][k]
// 256 thr = 8 warps x 16 weight-rows (NTILE=128). Whole X k-slice staged once.
// k-order permuted within each 16-group on BOTH operands so one LDG.128/row
// supplies the full A fragment.
#define XPAD 264   // bf16 row stride 528B: ldmatrix conflict-free, Kper<=256

__global__ void __launch_bounds__(256, 4) k_hmma(
    const float* __restrict__ W, const float* __restrict__ X,
    float* __restrict__ part, int N, int K, int Kper)
{
    __shared__ __align__(16) __nv_bfloat16 xhi[SEQ][XPAD];
    __shared__ __align__(16) __nv_bfloat16 xlo[SEQ][XPAD];
    const int tid  = threadIdx.x;
    const int lane = tid & 31;
    const int wid  = tid >> 5;
    const int g    = lane >> 2;
    const int tig  = lane & 3;
    const int nb   = blockIdx.x * 128;
    const int kbeg = blockIdx.y * Kper;

    {
        uint32_t* xh32 = (uint32_t*)&xhi[0][0];
        uint32_t* xl32 = (uint32_t*)&xlo[0][0];
        const int nf4 = Kper >> 2;
        for (int f = tid; f < SEQ * nf4; f += 256) {
            int s = f / nf4, c = f - s * nf4;
            int g16 = c >> 2, c4 = c & 3;
            int u0 = s * (XPAD / 2) + g16 * 8 + c4;
            float4 v = *(const float4*)(X + (size_t)s * K + kbeg + c * 4);
            xh32[u0]     = pack_hi(v.x, v.y);
            xh32[u0 + 4] = pack_hi(v.z, v.w);
            xl32[u0]     = pack_lo(v.x, v.y);
            xl32[u0 + 4] = pack_lo(v.z, v.w);
        }
    }
    __syncthreads();

    const float* wr0 = W + (size_t)(nb + wid * 16 + g) * K + kbeg + 4 * tig;
    const float* wr1 = wr0 + (size_t)8 * K;

    float acc[4][4];
#pragma unroll
    for (int t = 0; t < 4; t++)
#pragma unroll
        for (int r = 0; r < 4; r++) acc[t][r] = 0.f;

    const uint32_t lrow_hi = smem_to_u32(&xhi[0][0]) + lane * (XPAD * 2);
    const uint32_t lrow_lo = smem_to_u32(&xlo[0][0]) + lane * (XPAD * 2);

#pragma unroll 8
    for (int kk = 0; kk < Kper; kk += 16) {
        float4 w0 = *(const float4*)(wr0 + kk);
        float4 w1 = *(const float4*)(wr1 + kk);
        uint32_t ah[4], al[4];
        ah[0] = pack_hi(w0.x, w0.y); al[0] = pack_lo(w0.x, w0.y);
        ah[1] = pack_hi(w1.x, w1.y); al[1] = pack_lo(w1.x, w1.y);
        ah[2] = pack_hi(w0.z, w0.w); al[2] = pack_lo(w0.z, w0.w);
        ah[3] = pack_hi(w1.z, w1.w); al[3] = pack_lo(w1.z, w1.w);
        uint32_t bh0[4], bh1[4], bl0[4], bl1[4];
        LDSM4(bh0, lrow_hi + kk * 2);
        LDSM4(bh1, lrow_hi + kk * 2 + 16);
        LDSM4(bl0, lrow_lo + kk * 2);
        LDSM4(bl1, lrow_lo + kk * 2 + 16);
#pragma unroll
        for (int t = 0; t < 4; t++) {
            MMA16816(acc[t], ah, bh0[t], bh1[t]);
            MMA16816(acc[t], ah, bl0[t], bl1[t]);
            MMA16816(acc[t], al, bh0[t], bh1[t]);
        }
    }
    float* pb = part + (size_t)blockIdx.y * SEQ * N;
    const int n0 = nb + wid * 16 + g;
#pragma unroll
    for (int t = 0; t < 4; t++) {
        int s0 = t * 8 + 2 * tig;
        pb[(size_t)s0 * N + n0]           = acc[t][0];
        pb[(size_t)(s0 + 1) * N + n0]     = acc[t][1];
        pb[(size_t)s0 * N + n0 + 8]       = acc[t][2];
        pb[(size_t)(s0 + 1) * N + n0 + 8] = acc[t][3];
    }
}

// ---- split-K reduce, float4, 4-way unrolled (+bias, opt exact gelu) ------
__global__ void k_red4(const float4* __restrict__ part, const float4* __restrict__ bias,
                       float4* __restrict__ out, int N4, int kspl, int act)
{
    int idx = blockIdx.x * 256 + threadIdx.x;
    if (idx >= N4 * SEQ) return;
    int n = idx % N4;
    const size_t stride = (size_t)SEQ * N4;
    float4 a0 = make_float4(0, 0, 0, 0), a1 = a0, a2 = a0, a3 = a0;
    for (int z = 0; z < kspl; z += 4) {
        f4acc(a0, part[(size_t)z * stride + idx]);
        f4acc(a1, part[(size_t)(z + 1) * stride + idx]);
        f4acc(a2, part[(size_t)(z + 2) * stride + idx]);
        f4acc(a3, part[(size_t)(z + 3) * stride + idx]);
    }
    float4 v = bias[n];
    v.x += a0.x + a1.x + a2.x + a3.x;
    v.y += a0.y + a1.y + a2.y + a3.y;
    v.z += a0.z + a1.z + a2.z + a3.z;
    v.w += a0.w + a1.w + a2.w + a3.w;
    if (act) {
        v.x *= normcdff(v.x); v.y *= normcdff(v.y);
        v.z *= normcdff(v.z); v.w *= normcdff(v.w);
    }
    out[idx] = v;
}

// ---- scalar split-K reduce, 4-way unrolled (proj head) -------------------
__global__ void k_red_s(const float* __restrict__ part, const float* __restrict__ bias,
                        float* __restrict__ out, int N, int kspl)
{
    int idx = blockIdx.x * 256 + threadIdx.x;
    if (idx >= N * SEQ) return;
    int n = idx % N;
    const size_t stride = (size_t)SEQ * N;
    float a0 = 0, a1 = 0, a2 = 0, a3 = 0;
    for (int z = 0; z < kspl; z += 4) {
        a0 += part[(size_t)z * stride + idx];
        a1 += part[(size_t)(z + 1) * stride + idx];
        a2 += part[(size_t)(z + 2) * stride + idx];
        a3 += part[(size_t)(z + 3) * stride + idx];
    }
    out[idx] = bias[n] + a0 + a1 + a2 + a3;
}

// ---- fused split-K reduce + residual + LayerNorm, MLP-unrolled -----------
__global__ void __launch_bounds__(256) k_red_ln(
    const float4* __restrict__ part, const float4* __restrict__ bias,
    float4* __restrict__ x, const float4* __restrict__ g, const float4* __restrict__ b,
    int kspl)
{
    __shared__ float ssum[8], ssq[8], smr[2];
    const int s = blockIdx.x, t = threadIdx.x;
    const size_t stride = (size_t)SEQ * 512;
    const float4* pp = part + (size_t)s * 512 + t;

    float4 s00 = make_float4(0, 0, 0, 0), s01 = s00, s10 = s00, s11 = s00;
    for (int kz = 0; kz < kspl; kz += 2) {
        const float4* q0 = pp + (size_t)kz * stride;
        const float4* q1 = q0 + stride;
        f4acc(s00, q0[0]); f4acc(s01, q0[256]);
        f4acc(s10, q1[0]); f4acc(s11, q1[256]);
    }
    float4 z[2];
    float ls = 0.f, lq = 0.f;
#pragma unroll
    for (int j = 0; j < 2; j++) {
        int n4 = t + j * 256;
        size_t base = (size_t)s * 512 + n4;
        float4 v = bias[n4];
        float4 sa = (j == 0) ? s00 : s01;
        float4 sb = (j == 0) ? s10 : s11;
        v.x += sa.x + sb.x; v.y += sa.y + sb.y;
        v.z += sa.z + sb.z; v.w += sa.w + sb.w;
        float4 xx = x[base];
        float4 zz = make_float4(xx.x + v.x, xx.y + v.y, xx.z + v.z, xx.w + v.w);
        z[j] = zz;
        ls += zz.x + zz.y + zz.z + zz.w;
        lq += zz.x * zz.x + zz.y * zz.y + zz.z * zz.z + zz.w * zz.w;
    }
#pragma unroll
    for (int o = 16; o; o >>= 1) { ls += __shfl_xor_sync(~0u, ls, o); lq += __shfl_xor_sync(~0u, lq, o); }
    if ((t & 31) == 0) { ssum[t >> 5] = ls; ssq[t >> 5] = lq; }
    __syncthreads();
    if (t == 0) {
        float a = 0.f, q = 0.f;
#pragma unroll
        for (int w = 0; w < 8; w++) { a += ssum[w]; q += ssq[w]; }
        float m = a * (1.0f / HD);
        smr[0] = m;
        smr[1] = rsqrtf(q * (1.0f / HD) - m * m + 1e-5f);
    }
    __syncthreads();
    float m = smr[0], r = smr[1];
#pragma unroll
    for (int j = 0; j < 2; j++) {
        int n4 = t + j * 256;
        size_t base = (size_t)s * 512 + n4;
        float4 gg = g[n4], bb = b[n4], zz = z[j];
        x[base] = make_float4((zz.x - m) * r * gg.x + bb.x, (zz.y - m) * r * gg.y + bb.y,
                              (zz.z - m) * r * gg.z + bb.z, (zz.w - m) * r * gg.w + bb.w);
    }
}

// ---- broadcast-vector residual + LayerNorm (cross-attn path) -------------
__global__ void __launch_bounds__(256) k_lnvec(
    float4* __restrict__ x, const float4* __restrict__ add,
    const float4* __restrict__ g, const float4* __restrict__ b)
{
    __shared__ float ssum[8], ssq[8], smr[2];
    const int s = blockIdx.x, t = threadIdx.x;
    float4 z[2];
    float ls = 0.f, lq = 0.f;
#pragma unroll
    for (int j = 0; j < 2; j++) {
        int n4 = t + j * 256;
        size_t base = (size_t)s * 512 + n4;
        float4 xx = x[base], a = add[n4];
        float4 zz = make_float4(xx.x + a.x, xx.y + a.y, xx.z + a.z, xx.w + a.w);
        z[j] = zz;
        ls += zz.x + zz.y + zz.z + zz.w;
        lq += zz.x * zz.x + zz.y * zz.y + zz.z * zz.z + zz.w * zz.w;
    }
#pragma unroll
    for (int o = 16; o; o >>= 1) { ls += __shfl_xor_sync(~0u, ls, o); lq += __shfl_xor_sync(~0u, lq, o); }
    if ((t & 31) == 0) { ssum[t >> 5] = ls; ssq[t >> 5] = lq; }
    __syncthreads();
    if (t == 0) {
        float a = 0.f, q = 0.f;
#pragma unroll
        for (int w = 0; w < 8; w++) { a += ssum[w]; q += ssq[w]; }
        float m = a * (1.0f / HD);
        smr[0] = m;
        smr[1] = rsqrtf(q * (1.0f / HD) - m * m + 1e-5f);
    }
    __syncthreads();
    float m = smr[0], r = smr[1];
#pragma unroll
    for (int j = 0; j < 2; j++) {
        int n4 = t + j * 256;
        size_t base = (size_t)s * 512 + n4;
        float4 gg = g[n4], bb = b[n4], zz = z[j];
        x[base] = make_float4((zz.x - m) * r * gg.x + bb.x, (zz.y - m) * r * gg.y + bb.y,
                              (zz.z - m) * r * gg.z + bb.z, (zz.w - m) * r * gg.w + bb.w);
    }
}

// ---- batched GEMV over layers, K=2048 hardcoded/unrolled -----------------
__global__ void k_gemv3(const float* __restrict__ W, size_t ws,
                        const float* __restrict__ bias, size_t bs,
                        const float* __restrict__ vin, size_t vs,
                        float* __restrict__ vout, size_t os)
{
    int l    = blockIdx.y;
    int n    = blockIdx.x * 8 + (threadIdx.x >> 5);
    int lane = threadIdx.x & 31;
    const float* wr = W + l * ws + (size_t)n * HD;
    const float* vi = vin + l * vs;
    float s = 0.f;
#pragma unroll 4
    for (int it = 0; it < 16; it++) {
        int k = lane * 4 + it * 128;
        float4 w = *(const float4*)(wr + k);
        float4 x = *(const float4*)(vi + k);
        s += w.x * x.x + w.y * x.y + w.z * x.z + w.w * x.w;
    }
#pragma unroll
    for (int o = 16; o; o >>= 1) s += __shfl_xor_sync(~0u, s, o);
    if (lane == 0) vout[l * os + n] = s + bias[l * bs + n];
}

// ---- GEMV (size head), K=2048 hardcoded ----------------------------------
__global__ void k_gemv(const float* __restrict__ W, const float* __restrict__ bias,
                       const float* __restrict__ vin, float* __restrict__ vout, int act)
{
    int n    = blockIdx.x * 8 + (threadIdx.x >> 5);
    int lane = threadIdx.x & 31;
    const float* wr = W + (size_t)n * HD;
    float s = 0.f;
#pragma unroll 4
    for (int it = 0; it < 16; it++) {
        int k = lane * 4 + it * 128;
        float4 w = *(const float4*)(wr + k);
        float4 x = *(const float4*)(vin + k);
        s += w.x * x.x + w.y * x.y + w.z * x.z + w.w * x.w;
    }
#pragma unroll
    for (int o = 16; o; o >>= 1) s += __shfl_xor_sync(~0u, s, o);
    if (lane == 0) {
        float v = s + bias[n];
        if (act) v = v * normcdff(v);
        vout[n] = v;
    }
}

// ---- size-predictor: 33 logits + softmax ---------------------------------
__global__ void k_sp2(const float* __restrict__ w2, const float* __restrict__ b2,
                      const float* __restrict__ h1, float* __restrict__ outp)
{
    __shared__ float lg[33];
    int lane = threadIdx.x & 31, wid = threadIdx.x >> 5;
    for (int j = wid; j < 33; j += 8) {
        const float* wr = w2 + (size_t)j * 1024;
        float s = 0.f;
#pragma unroll 4
        for (int it = 0; it < 8; it++) {
            int k = lane * 4 + it * 128;
            float4 w = *(const float4*)(wr + k);
            float4 x = *(const float4*)(h1 + k);
            s += w.x * x.x + w.y * x.y + w.z * x.z + w.w * x.w;
        }
#pragma unroll
        for (int o = 16; o; o >>= 1) s += __shfl_xor_sync(~0u, s, o);
        if (lane == 0) lg[j] = s + b2[j];
    }
    __syncthreads();
    if (threadIdx.x == 0) {
        float m = lg[0];
        for (int j = 1; j < 33; j++) m = fmaxf(m, lg[j]);
        float e[33], se = 0.f;
        for (int j = 0; j < 33; j++) { e[j] = expf(lg[j] - m); se += e[j]; }
        float inv = 1.f / se;
        for (int j = 0; j < 33; j++) outp[j] = e[j] * inv;
    }
}

// ---- embedding (token-major) ---------------------------------------------
__global__ void k_embed(const int* __restrict__ tb, const float* __restrict__ bemb,
                        const float* __restrict__ pemb, float* __restrict__ x)
{
    int idx = blockIdx.x * 256 + threadIdx.x;
    int s = idx >> 11;
    int k = idx & 2047;
    int d = (s == 0) ? 256 : tb[s - 1];
    x[idx] = bemb[(size_t)d * HD + k] + pemb[idx];
}

// ---- self-attention, token-major, one block per head ---------------------
__global__ void __launch_bounds__(256) k_attn(const float* __restrict__ qkv,
                                              float* __restrict__ o)
{
    __shared__ float qs[32][129], ks[32][129], sc[32][33];
    const int h = blockIdx.x, t = threadIdx.x;
    float p0 = 0, p1 = 0, p2 = 0, p3 = 0;

    for (int dc = 0; dc < 256; dc += 128) {
        __syncthreads();
#pragma unroll
        for (int i = 0; i < 16; i++) {
            int idx = t + i * 256;
            int s = idx >> 7, d = idx & 127;
            qs[s][d] = qkv[s * 6144 + h * 256 + dc + d];
            ks[s][d] = qkv[s * 6144 + 2048 + h * 256 + dc + d];
        }
        __syncthreads();
        int qi = t >> 5, ki = t & 31;
        for (int d = 0; d < 128; d++) {
            float kv = ks[ki][d];
            p0 += qs[qi     ][d] * kv;
            p1 += qs[qi +  8][d] * kv;
            p2 += qs[qi + 16][d] * kv;
            p3 += qs[qi + 24][d] * kv;
        }
    }
    {
        int qi = t >> 5, ki = t & 31;
        sc[qi     ][ki] = p0 * 0.0625f;
        sc[qi +  8][ki] = p1 * 0.0625f;
        sc[qi + 16][ki] = p2 * 0.0625f;
        sc[qi + 24][ki] = p3 * 0.0625f;
    }
    __syncthreads();
    {
        int wid = t >> 5, lane = t & 31;
        for (int qi = wid; qi < 32; qi += 8) {
            float v = sc[qi][lane];
            float m = v;
#pragma unroll
            for (int off = 16; off; off >>= 1) m = fmaxf(m, __shfl_xor_sync(~0u, m, off));
            float e = expf(v - m);
            float ss = e;
#pragma unroll
            for (int off = 16; off; off >>= 1) ss += __shfl_xor_sync(~0u, ss, off);
            sc[qi][lane] = e / ss;
        }
    }
    for (int dc = 0; dc < 256; dc += 128) {
        __syncthreads();
#pragma unroll
        for (int i = 0; i < 16; i++) {
            int idx = t + i * 256;
            int s = idx >> 7, d = idx & 127;
            qs[s][d] = qkv[s * 6144 + 4096 + h * 256 + dc + d];
        }
        __syncthreads();
#pragma unroll
        for (int i = 0; i < 16; i++) {
            int idx = t + i * 256;
            int s = idx >> 7, d = idx & 127;
            float a = 0.f;
#pragma unroll
            for (int ki = 0; ki < 32; ki++) a += sc[s][ki] * qs[ki][d];
            o[s * HD + h * 256 + dc + d] = a;
        }
    }
}

// ===================== host orchestration =================================
static void run_hmma(const float* W, const float* X, float* gp, int N, int K, int kz)
{
    dim3 grid(N / 128, kz);
    k_hmma<<<grid, 256>>>(W, X, gp, N, K, K / kz);
}

extern "C" void kernel_launch(void* const* d_in, const int* in_sizes, int n_in,
                              void* d_out, int out_size)
{
    const float* pe      = (const float*)d_in[0];
    const int*   tb      = (const int*)  d_in[1];
    const float* sp_w1   = (const float*)d_in[2];
    const float* sp_b1   = (const float*)d_in[3];
    const float* sp_w2   = (const float*)d_in[4];
    const float* sp_b2   = (const float*)d_in[5];
    const float* bemb    = (const float*)d_in[6];
    const float* pemb    = (const float*)d_in[7];
    const float* proj_w  = (const float*)d_in[8];
    const float* proj_b  = (const float*)d_in[9];
    const float* sa_in_w = (const float*)d_in[10];
    const float* sa_in_b = (const float*)d_in[11];
    const float* sa_out_w= (const float*)d_in[12];
    const float* sa_out_b= (const float*)d_in[13];
    const float* ca_in_w = (const float*)d_in[14];
    const float* ca_in_b = (const float*)d_in[15];
    const float* ca_out_w= (const float*)d_in[16];
    const float* ca_out_b= (const float*)d_in[17];
    const float* ff_w1   = (const float*)d_in[18];
    const float* ff_b1   = (const float*)d_in[19];
    const float* ff_w2   = (const float*)d_in[20];
    const float* ff_b2   = (const float*)d_in[21];
    const float* ln1_g   = (const float*)d_in[22];
    const float* ln1_b   = (const float*)d_in[23];
    const float* ln2_g   = (const float*)d_in[24];
    const float* ln2_b   = (const float*)d_in[25];
    const float* ln3_g   = (const float*)d_in[26];
    const float* ln3_b   = (const float*)d_in[27];
    float* out = (float*)d_out;

    float *xp, *qkvp, *t8, *t2, *vc, *cc, *h1, *gp;
    cudaGetSymbolAddress((void**)&xp,   g_x);
    cudaGetSymbolAddress((void**)&qkvp, g_qkv);
    cudaGetSymbolAddress((void**)&t8,   g_t8);
    cudaGetSymbolAddress((void**)&t2,   g_t2);
    cudaGetSymbolAddress((void**)&vc,   g_vc);
    cudaGetSymbolAddress((void**)&cc,   g_cc);
    cudaGetSymbolAddress((void**)&h1,   g_h1);
    cudaGetSymbolAddress((void**)&gp,   g_gp);

    // size-predictor head -> out[0:33]
    k_gemv<<<1024 / 8, 256>>>(sp_w1, sp_b1, pe, h1, 1);
    k_sp2 <<<1, 256>>>(sp_w2, sp_b2, h1, out);

    // byte+pos embedding -> x (token-major)
    k_embed<<<(SEQ * HD) / 256, 256>>>(tb, bemb, pemb, xp);

    // cross-attention collapsed path, all 3 layers batched:
    // vc[l] = Wv_l . pe + bv_l ; cc[l] = Wout_l . vc[l] + bout_l
    {
        dim3 gv(HD / 8, 3);
        k_gemv3<<<gv, 256>>>(ca_in_w + (size_t)4096 * HD, (size_t)6144 * HD,
                             ca_in_b + 4096, 6144, pe, 0, vc, HD);
        k_gemv3<<<gv, 256>>>(ca_out_w, (size_t)HD * HD,
                             ca_out_b, HD, vc, HD, cc, HD);
    }

    for (int i = 0; i < 3; i++) {
        const float* saw  = sa_in_w  + (size_t)i * 6144 * HD;
        const float* sab  = sa_in_b  + (size_t)i * 6144;
        const float* sow  = sa_out_w + (size_t)i * HD * HD;
        const float* sob  = sa_out_b + (size_t)i * HD;
        const float* f1w  = ff_w1 + (size_t)i * 8192 * HD;
        const float* f1b  = ff_b1 + (size_t)i * 8192;
        const float* f2w  = ff_w2 + (size_t)i * HD * 8192;
        const float* f2b  = ff_b2 + (size_t)i * HD;

        // --- self-attention ---
        run_hmma(saw, xp, gp, 6144, HD, 16);                              // 768 blocks
        k_red4<<<(6144 * SEQ / 4 + 255) / 256, 256>>>((const float4*)gp, (const float4*)sab,
                                                      (float4*)qkvp, 6144 / 4, 16, 0);
        k_attn<<<8, 256>>>(qkvp, t2);
        run_hmma(sow, t2, gp, HD, HD, 32);                                // 512 blocks
        k_red_ln<<<SEQ, 256>>>((const float4*)gp, (const float4*)sob, (float4*)xp,
                               (const float4*)(ln1_g + i * HD), (const float4*)(ln1_b + i * HD), 32);

        // --- cross-attention (1 key -> softmax == 1; precomputed cc) ---
        k_lnvec<<<SEQ, 256>>>((float4*)xp, (const float4*)(cc + i * HD),
                              (const float4*)(ln2_g + i * HD), (const float4*)(ln2_b + i * HD));

        // --- feed-forward ---
        run_hmma(f1w, xp, gp, 8192, HD, 16);                              // 1024 blocks
        k_red4<<<(8192 * SEQ / 4 + 255) / 256, 256>>>((const float4*)gp, (const float4*)f1b,
                                                      (float4*)t8, 8192 / 4, 16, 1);
        run_hmma(f2w, t8, gp, HD, 8192, 32);                              // 512 blocks
        k_red_ln<<<SEQ, 256>>>((const float4*)gp, (const float4*)f2b, (float4*)xp,
                               (const float4*)(ln3_g + i * HD), (const float4*)(ln3_b + i * HD), 32);
    }

    // byte logits -> out[33:], row-major [s][256]
    run_hmma(proj_w, xp, gp, 256, HD, 32);                                // 64 blocks
    k_red_s<<<(256 * SEQ + 255) / 256, 256>>>(gp, proj_b, out + 33, 256, 32);
}